// round 11
// baseline (speedup 1.0000x reference)
#include <cuda_runtime.h>
#include <cuda_fp16.h>

// ---- static device scratch ----
// B fragments, paired-nt interleaved layout:
// uint4 index = ((chunk*16 + ntpair)*16 + kt)*32 + lane  -> B for two adjacent n-tiles
__device__ uint2 d_WGhi[192*16*32];
__device__ uint2 d_W1hi[16*16*32];
__device__ uint2 d_W1lo[16*16*32];
__device__ uint2 d_W2hi[16*8*32];
__device__ uint2 d_W2lo[16*8*32];
__device__ float d_Mi[768*2];
__device__ float d_ci[768];
__device__ unsigned char d_use[20*64];
__device__ int d_epsMode;

// ---- helpers ----
__device__ __forceinline__ unsigned packsplit(float v0, float v1, unsigned &lo) {
    __half h0 = __float2half(v0);
    __half h1 = __float2half(v1);
    __half l0 = __float2half(v0 - __half2float(h0));
    __half l1 = __float2half(v1 - __half2float(h1));
    lo = ((unsigned)__half_as_ushort(l1) << 16) | (unsigned)__half_as_ushort(l0);
    return ((unsigned)__half_as_ushort(h1) << 16) | (unsigned)__half_as_ushort(h0);
}
__device__ __forceinline__ int fidx(int r, int c, int KT) {
    return (((r >> 4) * KT + (c >> 4)) * 32 + (r & 7) * 4 + ((c & 7) >> 1)) * 4
           + ((r >> 3) & 1) + (((c >> 3) & 1) << 1);
}
__device__ __forceinline__ void mma16816(float (&c)[4], const uint4 a, const uint2 b) {
    asm volatile(
        "mma.sync.aligned.m16n8k16.row.col.f32.f16.f16.f32 "
        "{%0,%1,%2,%3},{%4,%5,%6,%7},{%8,%9},{%0,%1,%2,%3};\n"
        : "+f"(c[0]), "+f"(c[1]), "+f"(c[2]), "+f"(c[3])
        : "r"(a.x), "r"(a.y), "r"(a.z), "r"(a.w), "r"(b.x), "r"(b.y));
}
__device__ __forceinline__ float sigf(float x) {
    return __fdividef(1.f, 1.f + __expf(-x));
}
__device__ __forceinline__ float tanh_f(float x) {
    return 2.f * sigf(2.f * x) - 1.f;
}
__device__ __forceinline__ float eluf(float x) { return x > 0.f ? x : (__expf(x) - 1.f); }

// ---- setup ----
__global__ void s_detect(const unsigned char* eps) {
    __shared__ int s_ones, s_nz;
    if (threadIdx.x == 0) { s_ones = 0; s_nz = 0; }
    __syncthreads();
    int i = threadIdx.x;
    if (i < 768) {
        unsigned char b = eps[i];
        if ((i & 3) == 3 && b == 0x3f) atomicAdd(&s_ones, 1);
        if ((i & 3) != 0 && b != 0) atomicAdd(&s_nz, 1);
    }
    __syncthreads();
    if (threadIdx.x == 0)
        d_epsMode = (s_ones > 0) ? 2 : (s_nz == 0 ? 1 : 0);
}

__global__ void s_pack(const float* __restrict__ wh, const float* __restrict__ wi,
                       const float* __restrict__ w1, const float* __restrict__ w2,
                       const float* __restrict__ ew, const float* __restrict__ eb,
                       const float* __restrict__ bi, const unsigned char* __restrict__ eps) {
    int id = blockIdx.x * 256 + threadIdx.x;
    if (id < 98304) {
        // WG chunk layout: [0,768): Wh r,z,n; [768,1280): Wi+Wh r,z; [1280,1536): Wi n
        int lane = id & 31, kt = (id >> 5) & 15, gnt = id >> 9;   // gnt in 0..191
        int n = gnt * 8 + (lane >> 2);
        const float* sa;
        const float* sb = 0;
        if (n < 768)        { sa = wh + n * 256; }
        else if (n < 1280)  { sa = wi + (n - 768) * 256; sb = wh + (n - 768) * 256; }
        else                { sa = wi + (n - 1280 + 512) * 256; }
        int k0 = kt * 16 + (lane & 3) * 2;
        float v0 = sa[k0]     + (sb ? sb[k0]     : 0.f);
        float v1 = sa[k0+1]   + (sb ? sb[k0+1]   : 0.f);
        float v2 = sa[k0+8]   + (sb ? sb[k0+8]   : 0.f);
        float v3 = sa[k0+9]   + (sb ? sb[k0+9]   : 0.f);
        uint2 H;
        unsigned dummy;
        H.x = packsplit(v0, v1, dummy);
        H.y = packsplit(v2, v3, dummy);
        int chunk = gnt >> 5, nt = gnt & 31;
        int dest = ((chunk * 16 + (nt >> 1)) * 16 + kt) * 64 + lane * 2 + (nt & 1);
        d_WGhi[dest] = H;
    } else if (id < 106496) {              // W1: [128,256]
        int j = id - 98304;
        int lane = j & 31, kt = (j >> 5) & 15, nt = j >> 9;
        const float* src = w1 + (nt * 8 + (lane >> 2)) * 256;
        int k0 = kt * 16 + (lane & 3) * 2;
        uint2 H, L;
        H.x = packsplit(src[k0],   src[k0+1], L.x);
        H.y = packsplit(src[k0+8], src[k0+9], L.y);
        d_W1hi[j] = H; d_W1lo[j] = L;
    } else if (id < 110592) {              // W2: [128,128]
        int j = id - 106496;
        int lane = j & 31, kt = (j >> 5) & 7, nt = j >> 8;
        const float* src = w2 + (nt * 8 + (lane >> 2)) * 128;
        int k0 = kt * 16 + (lane & 3) * 2;
        uint2 H, L;
        H.x = packsplit(src[k0],   src[k0+1], L.x);
        H.y = packsplit(src[k0+8], src[k0+9], L.y);
        d_W2hi[j] = H; d_W2lo[j] = L;
    } else if (id < 111360) {              // Mi = Wi@embed_w, ci = Wi@embed_b + bi
        int n = id - 110592;
        const float* wr = wi + n * 256;
        float m0 = 0.f, m1 = 0.f, cc = 0.f;
        for (int k = 0; k < 256; k++) {
            float v = wr[k];
            m0 += v * ew[2*k]; m1 += v * ew[2*k+1]; cc += v * eb[k];
        }
        d_Mi[2*n] = m0; d_Mi[2*n+1] = m1; d_ci[n] = cc + bi[n];
    } else if (id < 112640) {              // d_use[t][a]
        int j = id - 111360;
        int t = j >> 6, a = j & 63;
        unsigned char u = 0;
        if (t >= 8) {
            int m = (t - 8) * 64 + a;
            int mode = d_epsMode;
            float v = (mode == 2) ? ((const float*)eps)[m]
                    : (mode == 1) ? (float)((const int*)eps)[m]
                    : (float)eps[m];
            u = (v != 0.f) ? 1 : 0;
        }
        d_use[j] = u;
    }
}

// =======================================================================
// Persistent fused kernel, 512 threads (16 warps -> 4/SMSP).
// CTA = 64 rows (agent, rz-half). h fragments live in SMEM for all 20 steps.
// Warp (wm, wn, wcg) covers 2 m-tiles x 2 n-tiles for cg = {wcg, wcg+2}.
// =======================================================================
extern __shared__ unsigned smem_u[];
__global__ void __launch_bounds__(512, 1) k_all(const float* __restrict__ inp,
                                                const float* __restrict__ bh,
                                                const float* __restrict__ bi,
                                                const float* __restrict__ b1,
                                                const float* __restrict__ b2,
                                                const float* __restrict__ w3,
                                                const float* __restrict__ b3,
                                                float* __restrict__ out) {
    uint4* hbuf = (uint4*)smem_u;            // 2 buffers x 4096 uint4 (hi 2048 | lo 2048)
    unsigned* fcmem = smem_u + 32768;        // 34048 bytes

    int am = blockIdx.x >> 1, rz = blockIdx.x & 1;
    int tid = threadIdx.x;
    int lane = tid & 31, w = tid >> 5;       // w in 0..15
    int wm = w & 1, wn = (w >> 1) & 3, wcg = w >> 3;   // 2 x 4 x 2
    int lane4 = lane >> 2;
    const uint4* WG4 = (const uint4*)d_WGhi;

    // h(0) = 0
    for (int i = tid; i < 4096; i += 512) hbuf[i] = make_uint4(0, 0, 0, 0);
    __syncthreads();

    int curb = 0;
    int lmt0 = wm * 2;                       // warp's first local m-tile (of 4)
    int a0 = (lmt0 * 16) * 32 + lane;        // uint4 idx in hi region at kt=0
    int a1 = a0 + 512;

    for (int t = 0; t < 20; t++) {
        bool full = d_use[t * 64 + am] != 0;
        const uint4* Ahi = hbuf + curb * 4096;
        const uint4* Alo = Ahi + 2048;
        unsigned* Whi = (unsigned*)(hbuf + (curb ^ 1) * 4096);
        unsigned* Wlo = Whi + 8192;
        const unsigned* RdHi = (const unsigned*)Ahi;
        const unsigned* RdLo = (const unsigned*)Alo;

        int chkR = full ? 3 : 0;
        int chkZ = full ? 4 : 1;

        // ---- 2 column-group iterations; 2 cgs in flight across warps ----
#pragma unroll
        for (int cgo = 0; cgo < 4; cgo += 2) {
            int cg = cgo + wcg;
            int ntp = cg * 4 + wn;           // n-tile pair (16 per chunk)
            int bR = ((chkR * 16 + ntp) * 16) * 32 + lane;
            int bZ = ((chkZ * 16 + ntp) * 16) * 32 + lane;
            int bN = ((2    * 16 + ntp) * 16) * 32 + lane;
            int bI = ((5    * 16 + ntp) * 16) * 32 + lane;

            float acc[2][2][4][4];
#pragma unroll
            for (int i = 0; i < 2; i++)
#pragma unroll
                for (int n = 0; n < 2; n++)
#pragma unroll
                    for (int g = 0; g < 4; g++)
#pragma unroll
                        for (int q = 0; q < 4; q++) acc[i][n][g][q] = 0.f;

            // prologue: B(0) register-prefetched (global/L2)
            uint4 WRc = WG4[bR], WZc = WG4[bZ], WNc = WG4[bN];

#pragma unroll 4
            for (int kt = 0; kt < 16; kt++) {
                int oc = kt * 32;
                int on = ((kt + 1 < 16) ? (kt + 1) : 15) * 32;
                // B prefetch for kt+1
                uint4 WRn = WG4[bR + on], WZn = WG4[bZ + on], WNn = WG4[bN + on];
                uint4 WIc;
                if (full) WIc = WG4[bI + oc];
                // A for current kt from SMEM (29cyc, hidden by 4 warps/SMSP)
                uint4 ahC0 = Ahi[a0 + oc], ahC1 = Ahi[a1 + oc];
                uint4 alC0 = Alo[a0 + oc], alC1 = Alo[a1 + oc];

                uint2 Br0 = make_uint2(WRc.x, WRc.y), Br1 = make_uint2(WRc.z, WRc.w);
                uint2 Bz0 = make_uint2(WZc.x, WZc.y), Bz1 = make_uint2(WZc.z, WZc.w);
                uint2 Bn0 = make_uint2(WNc.x, WNc.y), Bn1 = make_uint2(WNc.z, WNc.w);

                mma16816(acc[0][0][0], ahC0, Br0); mma16816(acc[1][0][0], ahC1, Br0);
                mma16816(acc[0][1][0], ahC0, Br1); mma16816(acc[1][1][0], ahC1, Br1);
                mma16816(acc[0][0][1], ahC0, Bz0); mma16816(acc[1][0][1], ahC1, Bz0);
                mma16816(acc[0][1][1], ahC0, Bz1); mma16816(acc[1][1][1], ahC1, Bz1);
                mma16816(acc[0][0][2], ahC0, Bn0); mma16816(acc[1][0][2], ahC1, Bn0);
                mma16816(acc[0][1][2], ahC0, Bn1); mma16816(acc[1][1][2], ahC1, Bn1);
                mma16816(acc[0][0][2], alC0, Bn0); mma16816(acc[1][0][2], alC1, Bn0);
                mma16816(acc[0][1][2], alC0, Bn1); mma16816(acc[1][1][2], alC1, Bn1);
                if (full) {
                    uint2 Bi0 = make_uint2(WIc.x, WIc.y), Bi1 = make_uint2(WIc.z, WIc.w);
                    mma16816(acc[0][0][3], ahC0, Bi0); mma16816(acc[1][0][3], ahC1, Bi0);
                    mma16816(acc[0][1][3], ahC0, Bi1); mma16816(acc[1][1][3], ahC1, Bi1);
                    mma16816(acc[0][0][3], alC0, Bi0); mma16816(acc[1][0][3], alC1, Bi0);
                    mma16816(acc[0][1][3], alC0, Bi1); mma16816(acc[1][1][3], alC1, Bi1);
                }
                WRc = WRn; WZc = WZn; WNc = WNn;
            }

            // ---- gate epilogue (h_old from SMEM frags hi+lo) ----
            int nt0 = cg * 8 + wn * 2;
            float bhr0[2], bhr1[2], bhz0[2], bhz1[2], bhn0[2], bhn1[2];
            float bir0[2], bir1[2], biz0[2], biz1[2], bin0[2], bin1[2];
            float M0a[2][3], M0b[2][3], M1a[2][3], M1b[2][3], C0[2][3], C1[2][3];
            int cc[2];
#pragma unroll
            for (int n = 0; n < 2; n++) {
                int c = (nt0 + n) * 8 + (lane & 3) * 2;
                cc[n] = c;
                bhr0[n] = bh[c];       bhr1[n] = bh[c + 1];
                bhz0[n] = bh[256 + c]; bhz1[n] = bh[257 + c];
                bhn0[n] = bh[512 + c]; bhn1[n] = bh[513 + c];
                if (full) {
                    bir0[n] = bi[c];       bir1[n] = bi[c + 1];
                    biz0[n] = bi[256 + c]; biz1[n] = bi[257 + c];
                    bin0[n] = bi[512 + c]; bin1[n] = bi[513 + c];
                } else {
#pragma unroll
                    for (int g = 0; g < 3; g++) {
                        int n0 = g * 256 + c;
                        M0a[n][g] = d_Mi[2*n0];     M0b[n][g] = d_Mi[2*n0 + 1];   C0[n][g] = d_ci[n0];
                        M1a[n][g] = d_Mi[2*n0 + 2]; M1b[n][g] = d_Mi[2*n0 + 3];   C1[n][g] = d_ci[n0 + 1];
                    }
                }
            }

#pragma unroll
            for (int i = 0; i < 2; i++) {
#pragma unroll
                for (int half = 0; half < 2; half++) {
                    int rloc = (lmt0 + i) * 16 + half * 8 + lane4;
                    int q0 = half * 2;
                    float x0 = 0.f, x1 = 0.f;
                    if (!full) {
                        int b = rz * 64 + rloc;
                        const float* ip = inp + ((b * 64 + am) * 20 + t) * 2;
                        x0 = ip[0]; x1 = ip[1];
                    }
#pragma unroll
                    for (int n = 0; n < 2; n++) {
                        int c = cc[n];
                        int widx = fidx(rloc, c, 16);
                        unsigned uh = RdHi[widx], ul = RdLo[widx];
                        __half2 hh = *(__half2*)&uh, hl = *(__half2*)&ul;
                        float hox = __half2float(__low2half(hh))  + __half2float(__low2half(hl));
                        float hoy = __half2float(__high2half(hh)) + __half2float(__high2half(hl));
                        float r0g, r1g, z0g, z1g, n0g, n1g;
                        if (full) {
                            r0g = sigf(acc[i][n][0][q0]   + bir0[n] + bhr0[n]);
                            r1g = sigf(acc[i][n][0][q0+1] + bir1[n] + bhr1[n]);
                            z0g = sigf(acc[i][n][1][q0]   + biz0[n] + bhz0[n]);
                            z1g = sigf(acc[i][n][1][q0+1] + biz1[n] + bhz1[n]);
                            n0g = tanh_f(acc[i][n][3][q0]   + bin0[n] + r0g * (acc[i][n][2][q0]   + bhn0[n]));
                            n1g = tanh_f(acc[i][n][3][q0+1] + bin1[n] + r1g * (acc[i][n][2][q0+1] + bhn1[n]));
                        } else {
                            float ir0 = x0 * M0a[n][0] + x1 * M0b[n][0] + C0[n][0];
                            float iz0 = x0 * M0a[n][1] + x1 * M0b[n][1] + C0[n][1];
                            float in0 = x0 * M0a[n][2] + x1 * M0b[n][2] + C0[n][2];
                            float ir1 = x0 * M1a[n][0] + x1 * M1b[n][0] + C1[n][0];
                            float iz1 = x0 * M1a[n][1] + x1 * M1b[n][1] + C1[n][1];
                            float in1 = x0 * M1a[n][2] + x1 * M1b[n][2] + C1[n][2];
                            r0g = sigf(ir0 + acc[i][n][0][q0]   + bhr0[n]);
                            r1g = sigf(ir1 + acc[i][n][0][q0+1] + bhr1[n]);
                            z0g = sigf(iz0 + acc[i][n][1][q0]   + bhz0[n]);
                            z1g = sigf(iz1 + acc[i][n][1][q0+1] + bhz1[n]);
                            n0g = tanh_f(in0 + r0g * (acc[i][n][2][q0]   + bhn0[n]));
                            n1g = tanh_f(in1 + r1g * (acc[i][n][2][q0+1] + bhn1[n]));
                        }
                        float h0 = (1.f - z0g) * n0g + z0g * hox;
                        float h1 = (1.f - z1g) * n1g + z1g * hoy;
                        unsigned lo, hi = packsplit(h0, h1, lo);
                        Whi[widx] = hi; Wlo[widx] = lo;
                    }
                }
            }
        }
        __syncthreads();       // h(t+1) complete in buffer curb^1
        curb ^= 1;

        // ================= inline FC head (t >= 8), 16 warps =================
        if (t >= 8) {
            const uint4* Fhi = hbuf + curb * 4096;
            const uint4* Flo = Fhi + 2048;
            unsigned* sY1hi = fcmem;           // 4096 u32
            unsigned* sY1lo = fcmem + 4096;    // 4096 u32
            float* sy2 = (float*)fcmem;        // 64*132 floats (reused after sync)

            int fm = w & 3, fn = w >> 2;       // 4 m-tiles x 4 n-quads

            // ---- fc1: warp = 1 m-tile x 4 n-tiles ----
            float fa[4][4];
#pragma unroll
            for (int j = 0; j < 4; j++)
#pragma unroll
                for (int q = 0; q < 4; q++) fa[j][q] = 0.f;
#pragma unroll 2
            for (int kt = 0; kt < 16; kt++) {
                int base = (fm * 16 + kt) * 32 + lane;
                uint4 ah = Fhi[base];
                uint4 al = Flo[base];
#pragma unroll
                for (int j = 0; j < 4; j++) {
                    int bb = ((fn * 4 + j) * 16 + kt) * 32 + lane;
                    uint2 Bh = d_W1hi[bb], Bl = d_W1lo[bb];
                    mma16816(fa[j], ah, Bh);
                    mma16816(fa[j], al, Bh);
                    mma16816(fa[j], ah, Bl);
                }
            }
#pragma unroll
            for (int j = 0; j < 4; j++) {
                int rr = fm * 16 + lane4;
                int cf = fn * 32 + j * 8 + (lane & 3) * 2;
                float bb0 = b1[cf], bb1 = b1[cf + 1];
                float v0 = eluf(fa[j][0] + bb0);
                float v1 = eluf(fa[j][1] + bb1);
                unsigned lo, hi = packsplit(v0, v1, lo);
                int widx = fidx(rr, cf, 8);
                sY1hi[widx] = hi; sY1lo[widx] = lo;
                v0 = eluf(fa[j][2] + bb0);
                v1 = eluf(fa[j][3] + bb1);
                hi = packsplit(v0, v1, lo);
                widx = fidx(rr + 8, cf, 8);
                sY1hi[widx] = hi; sY1lo[widx] = lo;
            }
            __syncthreads();

            // ---- fc2: warp = 1 m-tile x 4 n-tiles ----
            float fb[4][4];
#pragma unroll
            for (int j = 0; j < 4; j++)
#pragma unroll
                for (int q = 0; q < 4; q++) fb[j][q] = 0.f;
            const uint4* sY1hi4 = (const uint4*)sY1hi;
            const uint4* sY1lo4 = (const uint4*)sY1lo;
#pragma unroll 2
            for (int kt = 0; kt < 8; kt++) {
                int base = (fm * 8 + kt) * 32 + lane;
                uint4 ah = sY1hi4[base];
                uint4 al = sY1lo4[base];
#pragma unroll
                for (int j = 0; j < 4; j++) {
                    int bb = ((fn * 4 + j) * 8 + kt) * 32 + lane;
                    uint2 Bh = d_W2hi[bb], Bl = d_W2lo[bb];
                    mma16816(fb[j], ah, Bh);
                    mma16816(fb[j], al, Bh);
                    mma16816(fb[j], ah, Bl);
                }
            }
            __syncthreads();   // sY1 reads done before overwrite with y2

#pragma unroll
            for (int j = 0; j < 4; j++) {
                int rr = fm * 16 + lane4;
                int cf = fn * 32 + j * 8 + (lane & 3) * 2;
                float bb0 = b2[cf], bb1 = b2[cf + 1];
                sy2[rr * 132 + cf]           = eluf(fb[j][0] + bb0);
                sy2[rr * 132 + cf + 1]       = eluf(fb[j][1] + bb1);
                sy2[(rr + 8) * 132 + cf]     = eluf(fb[j][2] + bb0);
                sy2[(rr + 8) * 132 + cf + 1] = eluf(fb[j][3] + bb1);
            }
            __syncthreads();

            // ---- fc3 + gt mask ----
            if (tid < 128) {
                int rl = tid >> 1, cr = tid & 1;
                const float* wr = w3 + cr * 128;
                float s = b3[cr];
#pragma unroll 8
                for (int k = 0; k < 128; k++) s += sy2[rl * 132 + k] * __ldg(wr + k);
                int b = rz * 64 + rl;
                float gv = inp[((b * 64 + am) * 20 + t) * 2 + cr];
                out[((b * 64 + am) * 12 + (t - 8)) * 2 + cr] = (gv != 0.f) ? s : 0.f;
            }
            __syncthreads();   // fc3 reads done before next t's FC writes
        }
    }
}

extern "C" void kernel_launch(void* const* d_in, const int* in_sizes, int n_in,
                              void* d_out, int out_size) {
    int sh = (n_in >= 15 && in_sizes[1] <= 4) ? 0 : -1;
    const float* inputs = (const float*)d_in[0];
    const unsigned char* eps = (const unsigned char*)d_in[2 + sh];
    const float* ew = (const float*)d_in[3 + sh];
    const float* eb = (const float*)d_in[4 + sh];
    const float* wi = (const float*)d_in[5 + sh];
    const float* wh = (const float*)d_in[6 + sh];
    const float* bi = (const float*)d_in[7 + sh];
    const float* bh = (const float*)d_in[8 + sh];
    const float* w1 = (const float*)d_in[9 + sh];
    const float* b1 = (const float*)d_in[10 + sh];
    const float* w2 = (const float*)d_in[11 + sh];
    const float* b2 = (const float*)d_in[12 + sh];
    const float* w3 = (const float*)d_in[13 + sh];
    const float* b3 = (const float*)d_in[14 + sh];
    float* out = (float*)d_out;

    static int smem_set = 0;
    if (!smem_set) {
        cudaFuncSetAttribute(k_all, cudaFuncAttributeMaxDynamicSharedMemorySize, 165120);
        smem_set = 1;
    }

    s_detect<<<1, 768>>>(eps);
    s_pack<<<440, 256>>>(wh, wi, w1, w2, ew, eb, bi, eps);
    k_all<<<128, 512, 165120>>>(inputs, bh, bi, b1, b2, w3, b3, out);
}

// round 12
// speedup vs baseline: 1.0080x; 1.0080x over previous
#include <cuda_runtime.h>
#include <cuda_fp16.h>

// ---- static device scratch ----
// B fragments, paired-nt interleaved layout:
// uint4 index = ((chunk*16 + ntpair)*16 + kt)*32 + lane  -> B for two adjacent n-tiles
__device__ uint2 d_WGhi[192*16*32];
__device__ uint2 d_W1hi[16*16*32];
__device__ uint2 d_W1lo[16*16*32];
__device__ uint2 d_W2hi[16*8*32];
__device__ uint2 d_W2lo[16*8*32];
__device__ float d_Mi[768*2];
__device__ float d_ci[768];
__device__ unsigned char d_use[20*64];
__device__ int d_epsMode;

// ---- helpers ----
__device__ __forceinline__ unsigned packsplit(float v0, float v1, unsigned &lo) {
    __half h0 = __float2half(v0);
    __half h1 = __float2half(v1);
    __half l0 = __float2half(v0 - __half2float(h0));
    __half l1 = __float2half(v1 - __half2float(h1));
    lo = ((unsigned)__half_as_ushort(l1) << 16) | (unsigned)__half_as_ushort(l0);
    return ((unsigned)__half_as_ushort(h1) << 16) | (unsigned)__half_as_ushort(h0);
}
__device__ __forceinline__ int fidx(int r, int c, int KT) {
    return (((r >> 4) * KT + (c >> 4)) * 32 + (r & 7) * 4 + ((c & 7) >> 1)) * 4
           + ((r >> 3) & 1) + (((c >> 3) & 1) << 1);
}
__device__ __forceinline__ void mma16816(float (&c)[4], const uint4 a, const uint2 b) {
    asm volatile(
        "mma.sync.aligned.m16n8k16.row.col.f32.f16.f16.f32 "
        "{%0,%1,%2,%3},{%4,%5,%6,%7},{%8,%9},{%0,%1,%2,%3};\n"
        : "+f"(c[0]), "+f"(c[1]), "+f"(c[2]), "+f"(c[3])
        : "r"(a.x), "r"(a.y), "r"(a.z), "r"(a.w), "r"(b.x), "r"(b.y));
}
__device__ __forceinline__ float sigf(float x) {
    return __fdividef(1.f, 1.f + __expf(-x));
}
__device__ __forceinline__ float tanh_f(float x) {
    return 2.f * sigf(2.f * x) - 1.f;
}
__device__ __forceinline__ float eluf(float x) { return x > 0.f ? x : (__expf(x) - 1.f); }

// ---- setup ----
__global__ void s_detect(const unsigned char* eps) {
    __shared__ int s_ones, s_nz;
    if (threadIdx.x == 0) { s_ones = 0; s_nz = 0; }
    __syncthreads();
    int i = threadIdx.x;
    if (i < 768) {
        unsigned char b = eps[i];
        if ((i & 3) == 3 && b == 0x3f) atomicAdd(&s_ones, 1);
        if ((i & 3) != 0 && b != 0) atomicAdd(&s_nz, 1);
    }
    __syncthreads();
    if (threadIdx.x == 0)
        d_epsMode = (s_ones > 0) ? 2 : (s_nz == 0 ? 1 : 0);
}

__global__ void s_pack(const float* __restrict__ wh, const float* __restrict__ wi,
                       const float* __restrict__ w1, const float* __restrict__ w2,
                       const float* __restrict__ ew, const float* __restrict__ eb,
                       const float* __restrict__ bi, const unsigned char* __restrict__ eps) {
    int id = blockIdx.x * 256 + threadIdx.x;
    if (id < 98304) {
        // WG chunk layout: [0,768): Wh r,z,n; [768,1280): Wi+Wh r,z; [1280,1536): Wi n
        int lane = id & 31, kt = (id >> 5) & 15, gnt = id >> 9;   // gnt in 0..191
        int n = gnt * 8 + (lane >> 2);
        const float* sa;
        const float* sb = 0;
        if (n < 768)        { sa = wh + n * 256; }
        else if (n < 1280)  { sa = wi + (n - 768) * 256; sb = wh + (n - 768) * 256; }
        else                { sa = wi + (n - 1280 + 512) * 256; }
        int k0 = kt * 16 + (lane & 3) * 2;
        float v0 = sa[k0]     + (sb ? sb[k0]     : 0.f);
        float v1 = sa[k0+1]   + (sb ? sb[k0+1]   : 0.f);
        float v2 = sa[k0+8]   + (sb ? sb[k0+8]   : 0.f);
        float v3 = sa[k0+9]   + (sb ? sb[k0+9]   : 0.f);
        uint2 H;
        unsigned dummy;
        H.x = packsplit(v0, v1, dummy);
        H.y = packsplit(v2, v3, dummy);
        int chunk = gnt >> 5, nt = gnt & 31;
        int dest = ((chunk * 16 + (nt >> 1)) * 16 + kt) * 64 + lane * 2 + (nt & 1);
        d_WGhi[dest] = H;
    } else if (id < 106496) {              // W1: [128,256]
        int j = id - 98304;
        int lane = j & 31, kt = (j >> 5) & 15, nt = j >> 9;
        const float* src = w1 + (nt * 8 + (lane >> 2)) * 256;
        int k0 = kt * 16 + (lane & 3) * 2;
        uint2 H, L;
        H.x = packsplit(src[k0],   src[k0+1], L.x);
        H.y = packsplit(src[k0+8], src[k0+9], L.y);
        d_W1hi[j] = H; d_W1lo[j] = L;
    } else if (id < 110592) {              // W2: [128,128]
        int j = id - 106496;
        int lane = j & 31, kt = (j >> 5) & 7, nt = j >> 8;
        const float* src = w2 + (nt * 8 + (lane >> 2)) * 128;
        int k0 = kt * 16 + (lane & 3) * 2;
        uint2 H, L;
        H.x = packsplit(src[k0],   src[k0+1], L.x);
        H.y = packsplit(src[k0+8], src[k0+9], L.y);
        d_W2hi[j] = H; d_W2lo[j] = L;
    } else if (id < 111360) {              // Mi = Wi@embed_w, ci = Wi@embed_b + bi
        int n = id - 110592;
        const float* wr = wi + n * 256;
        float m0 = 0.f, m1 = 0.f, cc = 0.f;
        for (int k = 0; k < 256; k++) {
            float v = wr[k];
            m0 += v * ew[2*k]; m1 += v * ew[2*k+1]; cc += v * eb[k];
        }
        d_Mi[2*n] = m0; d_Mi[2*n+1] = m1; d_ci[n] = cc + bi[n];
    } else if (id < 112640) {              // d_use[t][a]
        int j = id - 111360;
        int t = j >> 6, a = j & 63;
        unsigned char u = 0;
        if (t >= 8) {
            int m = (t - 8) * 64 + a;
            int mode = d_epsMode;
            float v = (mode == 2) ? ((const float*)eps)[m]
                    : (mode == 1) ? (float)((const int*)eps)[m]
                    : (float)eps[m];
            u = (v != 0.f) ? 1 : 0;
        }
        d_use[j] = u;
    }
}

// =======================================================================
// Persistent fused kernel, 512 threads (16 warps -> 4/SMSP).
// CTA = 64 rows (agent, rz-half). h fragments live in SMEM for all 20 steps.
// Warp (wm, wn, wcg) covers 2 m-tiles x 2 n-tiles for cg = {wcg, wcg+2}.
// =======================================================================
extern __shared__ unsigned smem_u[];
__global__ void __launch_bounds__(512, 1) k_all(const float* __restrict__ inp,
                                                const float* __restrict__ bh,
                                                const float* __restrict__ bi,
                                                const float* __restrict__ b1,
                                                const float* __restrict__ b2,
                                                const float* __restrict__ w3,
                                                const float* __restrict__ b3,
                                                float* __restrict__ out) {
    uint4* hbuf = (uint4*)smem_u;            // 2 buffers x 4096 uint4 (hi 2048 | lo 2048)
    unsigned* fcmem = smem_u + 32768;        // 34048 bytes

    int am = blockIdx.x >> 1, rz = blockIdx.x & 1;
    int tid = threadIdx.x;
    int lane = tid & 31, w = tid >> 5;       // w in 0..15
    int wm = w & 1, wn = (w >> 1) & 3, wcg = w >> 3;   // 2 x 4 x 2
    int lane4 = lane >> 2;
    const uint4* WG4 = (const uint4*)d_WGhi;

    // h(0) = 0
    for (int i = tid; i < 4096; i += 512) hbuf[i] = make_uint4(0, 0, 0, 0);
    __syncthreads();

    int curb = 0;
    int lmt0 = wm * 2;                       // warp's first local m-tile (of 4)
    int a0 = (lmt0 * 16) * 32 + lane;        // uint4 idx in hi region at kt=0
    int a1 = a0 + 512;

    for (int t = 0; t < 20; t++) {
        bool full = d_use[t * 64 + am] != 0;
        const uint4* Ahi = hbuf + curb * 4096;
        const uint4* Alo = Ahi + 2048;
        unsigned* Whi = (unsigned*)(hbuf + (curb ^ 1) * 4096);
        unsigned* Wlo = Whi + 8192;
        const unsigned* RdHi = (const unsigned*)Ahi;
        const unsigned* RdLo = (const unsigned*)Alo;

        int chkR = full ? 3 : 0;
        int chkZ = full ? 4 : 1;

        // ---- 2 column-group iterations; 2 cgs in flight across warps ----
#pragma unroll
        for (int cgo = 0; cgo < 4; cgo += 2) {
            int cg = cgo + wcg;
            int ntp = cg * 4 + wn;           // n-tile pair (16 per chunk)
            int bR = ((chkR * 16 + ntp) * 16) * 32 + lane;
            int bZ = ((chkZ * 16 + ntp) * 16) * 32 + lane;
            int bN = ((2    * 16 + ntp) * 16) * 32 + lane;
            int bI = ((5    * 16 + ntp) * 16) * 32 + lane;

            float acc[2][2][4][4];
#pragma unroll
            for (int i = 0; i < 2; i++)
#pragma unroll
                for (int n = 0; n < 2; n++)
#pragma unroll
                    for (int g = 0; g < 4; g++)
#pragma unroll
                        for (int q = 0; q < 4; q++) acc[i][n][g][q] = 0.f;

            // prologue: B(0) register-prefetched (global/L2)
            uint4 WRc = WG4[bR], WZc = WG4[bZ], WNc = WG4[bN];

#pragma unroll 4
            for (int kt = 0; kt < 16; kt++) {
                int oc = kt * 32;
                int on = ((kt + 1 < 16) ? (kt + 1) : 15) * 32;
                // B prefetch for kt+1
                uint4 WRn = WG4[bR + on], WZn = WG4[bZ + on], WNn = WG4[bN + on];
                uint4 WIc;
                if (full) WIc = WG4[bI + oc];
                // A for current kt from SMEM (29cyc, hidden by 4 warps/SMSP)
                uint4 ahC0 = Ahi[a0 + oc], ahC1 = Ahi[a1 + oc];
                uint4 alC0 = Alo[a0 + oc], alC1 = Alo[a1 + oc];

                uint2 Br0 = make_uint2(WRc.x, WRc.y), Br1 = make_uint2(WRc.z, WRc.w);
                uint2 Bz0 = make_uint2(WZc.x, WZc.y), Bz1 = make_uint2(WZc.z, WZc.w);
                uint2 Bn0 = make_uint2(WNc.x, WNc.y), Bn1 = make_uint2(WNc.z, WNc.w);

                mma16816(acc[0][0][0], ahC0, Br0); mma16816(acc[1][0][0], ahC1, Br0);
                mma16816(acc[0][1][0], ahC0, Br1); mma16816(acc[1][1][0], ahC1, Br1);
                mma16816(acc[0][0][1], ahC0, Bz0); mma16816(acc[1][0][1], ahC1, Bz0);
                mma16816(acc[0][1][1], ahC0, Bz1); mma16816(acc[1][1][1], ahC1, Bz1);
                mma16816(acc[0][0][2], ahC0, Bn0); mma16816(acc[1][0][2], ahC1, Bn0);
                mma16816(acc[0][1][2], ahC0, Bn1); mma16816(acc[1][1][2], ahC1, Bn1);
                mma16816(acc[0][0][2], alC0, Bn0); mma16816(acc[1][0][2], alC1, Bn0);
                mma16816(acc[0][1][2], alC0, Bn1); mma16816(acc[1][1][2], alC1, Bn1);
                if (full) {
                    uint2 Bi0 = make_uint2(WIc.x, WIc.y), Bi1 = make_uint2(WIc.z, WIc.w);
                    mma16816(acc[0][0][3], ahC0, Bi0); mma16816(acc[1][0][3], ahC1, Bi0);
                    mma16816(acc[0][1][3], ahC0, Bi1); mma16816(acc[1][1][3], ahC1, Bi1);
                    mma16816(acc[0][0][3], alC0, Bi0); mma16816(acc[1][0][3], alC1, Bi0);
                    mma16816(acc[0][1][3], alC0, Bi1); mma16816(acc[1][1][3], alC1, Bi1);
                }
                WRc = WRn; WZc = WZn; WNc = WNn;
            }

            // ---- gate epilogue (h_old from SMEM frags hi+lo) ----
            int nt0 = cg * 8 + wn * 2;
            float bhr0[2], bhr1[2], bhz0[2], bhz1[2], bhn0[2], bhn1[2];
            float bir0[2], bir1[2], biz0[2], biz1[2], bin0[2], bin1[2];
            float M0a[2][3], M0b[2][3], M1a[2][3], M1b[2][3], C0[2][3], C1[2][3];
            int cc[2];
#pragma unroll
            for (int n = 0; n < 2; n++) {
                int c = (nt0 + n) * 8 + (lane & 3) * 2;
                cc[n] = c;
                bhr0[n] = bh[c];       bhr1[n] = bh[c + 1];
                bhz0[n] = bh[256 + c]; bhz1[n] = bh[257 + c];
                bhn0[n] = bh[512 + c]; bhn1[n] = bh[513 + c];
                if (full) {
                    bir0[n] = bi[c];       bir1[n] = bi[c + 1];
                    biz0[n] = bi[256 + c]; biz1[n] = bi[257 + c];
                    bin0[n] = bi[512 + c]; bin1[n] = bi[513 + c];
                } else {
#pragma unroll
                    for (int g = 0; g < 3; g++) {
                        int n0 = g * 256 + c;
                        M0a[n][g] = d_Mi[2*n0];     M0b[n][g] = d_Mi[2*n0 + 1];   C0[n][g] = d_ci[n0];
                        M1a[n][g] = d_Mi[2*n0 + 2]; M1b[n][g] = d_Mi[2*n0 + 3];   C1[n][g] = d_ci[n0 + 1];
                    }
                }
            }

#pragma unroll
            for (int i = 0; i < 2; i++) {
#pragma unroll
                for (int half = 0; half < 2; half++) {
                    int rloc = (lmt0 + i) * 16 + half * 8 + lane4;
                    int q0 = half * 2;
                    float x0 = 0.f, x1 = 0.f;
                    if (!full) {
                        int b = rz * 64 + rloc;
                        const float* ip = inp + ((b * 64 + am) * 20 + t) * 2;
                        x0 = ip[0]; x1 = ip[1];
                    }
#pragma unroll
                    for (int n = 0; n < 2; n++) {
                        int c = cc[n];
                        int widx = fidx(rloc, c, 16);
                        unsigned uh = RdHi[widx], ul = RdLo[widx];
                        __half2 hh = *(__half2*)&uh, hl = *(__half2*)&ul;
                        float hox = __half2float(__low2half(hh))  + __half2float(__low2half(hl));
                        float hoy = __half2float(__high2half(hh)) + __half2float(__high2half(hl));
                        float r0g, r1g, z0g, z1g, n0g, n1g;
                        if (full) {
                            r0g = sigf(acc[i][n][0][q0]   + bir0[n] + bhr0[n]);
                            r1g = sigf(acc[i][n][0][q0+1] + bir1[n] + bhr1[n]);
                            z0g = sigf(acc[i][n][1][q0]   + biz0[n] + bhz0[n]);
                            z1g = sigf(acc[i][n][1][q0+1] + biz1[n] + bhz1[n]);
                            n0g = tanh_f(acc[i][n][3][q0]   + bin0[n] + r0g * (acc[i][n][2][q0]   + bhn0[n]));
                            n1g = tanh_f(acc[i][n][3][q0+1] + bin1[n] + r1g * (acc[i][n][2][q0+1] + bhn1[n]));
                        } else {
                            float ir0 = x0 * M0a[n][0] + x1 * M0b[n][0] + C0[n][0];
                            float iz0 = x0 * M0a[n][1] + x1 * M0b[n][1] + C0[n][1];
                            float in0 = x0 * M0a[n][2] + x1 * M0b[n][2] + C0[n][2];
                            float ir1 = x0 * M1a[n][0] + x1 * M1b[n][0] + C1[n][0];
                            float iz1 = x0 * M1a[n][1] + x1 * M1b[n][1] + C1[n][1];
                            float in1 = x0 * M1a[n][2] + x1 * M1b[n][2] + C1[n][2];
                            r0g = sigf(ir0 + acc[i][n][0][q0]   + bhr0[n]);
                            r1g = sigf(ir1 + acc[i][n][0][q0+1] + bhr1[n]);
                            z0g = sigf(iz0 + acc[i][n][1][q0]   + bhz0[n]);
                            z1g = sigf(iz1 + acc[i][n][1][q0+1] + bhz1[n]);
                            n0g = tanh_f(in0 + r0g * (acc[i][n][2][q0]   + bhn0[n]));
                            n1g = tanh_f(in1 + r1g * (acc[i][n][2][q0+1] + bhn1[n]));
                        }
                        float h0 = (1.f - z0g) * n0g + z0g * hox;
                        float h1 = (1.f - z1g) * n1g + z1g * hoy;
                        unsigned lo, hi = packsplit(h0, h1, lo);
                        Whi[widx] = hi; Wlo[widx] = lo;
                    }
                }
            }
        }
        __syncthreads();       // h(t+1) complete in buffer curb^1
        curb ^= 1;

        // ================= inline FC head (t >= 8), 16 warps =================
        if (t >= 8) {
            const uint4* Fhi = hbuf + curb * 4096;
            const uint4* Flo = Fhi + 2048;
            unsigned* sY1hi = fcmem;           // 4096 u32
            unsigned* sY1lo = fcmem + 4096;    // 4096 u32
            float* sy2 = (float*)fcmem;        // 64*132 floats (reused after sync)

            int fm = w & 3, fn = w >> 2;       // 4 m-tiles x 4 n-quads

            // ---- fc1: warp = 1 m-tile x 4 n-tiles ----
            float fa[4][4];
#pragma unroll
            for (int j = 0; j < 4; j++)
#pragma unroll
                for (int q = 0; q < 4; q++) fa[j][q] = 0.f;
#pragma unroll 2
            for (int kt = 0; kt < 16; kt++) {
                int base = (fm * 16 + kt) * 32 + lane;
                uint4 ah = Fhi[base];
                uint4 al = Flo[base];
#pragma unroll
                for (int j = 0; j < 4; j++) {
                    int bb = ((fn * 4 + j) * 16 + kt) * 32 + lane;
                    uint2 Bh = d_W1hi[bb], Bl = d_W1lo[bb];
                    mma16816(fa[j], ah, Bh);
                    mma16816(fa[j], al, Bh);
                    mma16816(fa[j], ah, Bl);
                }
            }
#pragma unroll
            for (int j = 0; j < 4; j++) {
                int rr = fm * 16 + lane4;
                int cf = fn * 32 + j * 8 + (lane & 3) * 2;
                float bb0 = b1[cf], bb1 = b1[cf + 1];
                float v0 = eluf(fa[j][0] + bb0);
                float v1 = eluf(fa[j][1] + bb1);
                unsigned lo, hi = packsplit(v0, v1, lo);
                int widx = fidx(rr, cf, 8);
                sY1hi[widx] = hi; sY1lo[widx] = lo;
                v0 = eluf(fa[j][2] + bb0);
                v1 = eluf(fa[j][3] + bb1);
                hi = packsplit(v0, v1, lo);
                widx = fidx(rr + 8, cf, 8);
                sY1hi[widx] = hi; sY1lo[widx] = lo;
            }
            __syncthreads();

            // ---- fc2: warp = 1 m-tile x 4 n-tiles ----
            float fb[4][4];
#pragma unroll
            for (int j = 0; j < 4; j++)
#pragma unroll
                for (int q = 0; q < 4; q++) fb[j][q] = 0.f;
            const uint4* sY1hi4 = (const uint4*)sY1hi;
            const uint4* sY1lo4 = (const uint4*)sY1lo;
#pragma unroll 2
            for (int kt = 0; kt < 8; kt++) {
                int base = (fm * 8 + kt) * 32 + lane;
                uint4 ah = sY1hi4[base];
                uint4 al = sY1lo4[base];
#pragma unroll
                for (int j = 0; j < 4; j++) {
                    int bb = ((fn * 4 + j) * 8 + kt) * 32 + lane;
                    uint2 Bh = d_W2hi[bb], Bl = d_W2lo[bb];
                    mma16816(fb[j], ah, Bh);
                    mma16816(fb[j], al, Bh);
                    mma16816(fb[j], ah, Bl);
                }
            }
            __syncthreads();   // sY1 reads done before overwrite with y2

#pragma unroll
            for (int j = 0; j < 4; j++) {
                int rr = fm * 16 + lane4;
                int cf = fn * 32 + j * 8 + (lane & 3) * 2;
                float bb0 = b2[cf], bb1 = b2[cf + 1];
                sy2[rr * 132 + cf]           = eluf(fb[j][0] + bb0);
                sy2[rr * 132 + cf + 1]       = eluf(fb[j][1] + bb1);
                sy2[(rr + 8) * 132 + cf]     = eluf(fb[j][2] + bb0);
                sy2[(rr + 8) * 132 + cf + 1] = eluf(fb[j][3] + bb1);
            }
            __syncthreads();

            // ---- fc3 + gt mask ----
            if (tid < 128) {
                int rl = tid >> 1, cr = tid & 1;
                const float* wr = w3 + cr * 128;
                float s = b3[cr];
#pragma unroll 8
                for (int k = 0; k < 128; k++) s += sy2[rl * 132 + k] * __ldg(wr + k);
                int b = rz * 64 + rl;
                float gv = inp[((b * 64 + am) * 20 + t) * 2 + cr];
                out[((b * 64 + am) * 12 + (t - 8)) * 2 + cr] = (gv != 0.f) ? s : 0.f;
            }
            __syncthreads();   // fc3 reads done before next t's FC writes
        }
    }
}

extern "C" void kernel_launch(void* const* d_in, const int* in_sizes, int n_in,
                              void* d_out, int out_size) {
    int sh = (n_in >= 15 && in_sizes[1] <= 4) ? 0 : -1;
    const float* inputs = (const float*)d_in[0];
    const unsigned char* eps = (const unsigned char*)d_in[2 + sh];
    const float* ew = (const float*)d_in[3 + sh];
    const float* eb = (const float*)d_in[4 + sh];
    const float* wi = (const float*)d_in[5 + sh];
    const float* wh = (const float*)d_in[6 + sh];
    const float* bi = (const float*)d_in[7 + sh];
    const float* bh = (const float*)d_in[8 + sh];
    const float* w1 = (const float*)d_in[9 + sh];
    const float* b1 = (const float*)d_in[10 + sh];
    const float* w2 = (const float*)d_in[11 + sh];
    const float* b2 = (const float*)d_in[12 + sh];
    const float* w3 = (const float*)d_in[13 + sh];
    const float* b3 = (const float*)d_in[14 + sh];
    float* out = (float*)d_out;

    static int smem_set = 0;
    if (!smem_set) {
        cudaFuncSetAttribute(k_all, cudaFuncAttributeMaxDynamicSharedMemorySize, 165120);
        smem_set = 1;
    }

    s_detect<<<1, 768>>>(eps);
    s_pack<<<440, 256>>>(wh, wi, w1, w2, ew, eb, bi, eps);
    k_all<<<128, 512, 165120>>>(inputs, bh, bi, b1, b2, w3, b3, out);
}

// round 14
// speedup vs baseline: 1.0437x; 1.0354x over previous
#include <cuda_runtime.h>
#include <cuda_fp16.h>

// ---- static device scratch ----
__device__ uint2 d_WGhi[192*16*32];   // GRU B frags, paired-nt interleaved
__device__ uint2 d_W1hi[16*16*32];
__device__ uint2 d_W2hi[16*8*32];
__device__ float d_Mi[768*2];
__device__ float d_ci[768];

// ---- helpers ----
__device__ __forceinline__ unsigned packsplit(float v0, float v1, unsigned &lo) {
    __half h0 = __float2half(v0);
    __half h1 = __float2half(v1);
    __half l0 = __float2half(v0 - __half2float(h0));
    __half l1 = __float2half(v1 - __half2float(h1));
    lo = ((unsigned)__half_as_ushort(l1) << 16) | (unsigned)__half_as_ushort(l0);
    return ((unsigned)__half_as_ushort(h1) << 16) | (unsigned)__half_as_ushort(h0);
}
__device__ __forceinline__ int fidx(int r, int c, int KT) {
    return (((r >> 4) * KT + (c >> 4)) * 32 + (r & 7) * 4 + ((c & 7) >> 1)) * 4
           + ((r >> 3) & 1) + (((c >> 3) & 1) << 1);
}
__device__ __forceinline__ void mma16816(float (&c)[4], const uint4 a, const uint2 b) {
    asm volatile(
        "mma.sync.aligned.m16n8k16.row.col.f32.f16.f16.f32 "
        "{%0,%1,%2,%3},{%4,%5,%6,%7},{%8,%9},{%0,%1,%2,%3};\n"
        : "+f"(c[0]), "+f"(c[1]), "+f"(c[2]), "+f"(c[3])
        : "r"(a.x), "r"(a.y), "r"(a.z), "r"(a.w), "r"(b.x), "r"(b.y));
}
__device__ __forceinline__ float sigf(float x) { return __fdividef(1.f, 1.f + __expf(-x)); }
__device__ __forceinline__ float tanh_f(float x) { return 2.f * sigf(2.f * x) - 1.f; }
__device__ __forceinline__ float eluf(float x) { return x > 0.f ? x : (__expf(x) - 1.f); }

// ---- setup: pack weights (no eps handling here anymore) ----
__global__ void s_pack(const float* __restrict__ wh, const float* __restrict__ wi,
                       const float* __restrict__ w1, const float* __restrict__ w2,
                       const float* __restrict__ ew, const float* __restrict__ eb,
                       const float* __restrict__ bi) {
    int id = blockIdx.x * 256 + threadIdx.x;
    if (id < 98304) {
        // WG chunk layout: [0,768): Wh r,z,n; [768,1280): Wi+Wh r,z; [1280,1536): Wi n
        int lane = id & 31, kt = (id >> 5) & 15, gnt = id >> 9;   // gnt in 0..191
        int n = gnt * 8 + (lane >> 2);
        const float* sa;
        const float* sb = 0;
        if (n < 768)        { sa = wh + n * 256; }
        else if (n < 1280)  { sa = wi + (n - 768) * 256; sb = wh + (n - 768) * 256; }
        else                { sa = wi + (n - 1280 + 512) * 256; }
        int k0 = kt * 16 + (lane & 3) * 2;
        float v0 = sa[k0]     + (sb ? sb[k0]     : 0.f);
        float v1 = sa[k0+1]   + (sb ? sb[k0+1]   : 0.f);
        float v2 = sa[k0+8]   + (sb ? sb[k0+8]   : 0.f);
        float v3 = sa[k0+9]   + (sb ? sb[k0+9]   : 0.f);
        uint2 H;
        unsigned dummy;
        H.x = packsplit(v0, v1, dummy);
        H.y = packsplit(v2, v3, dummy);
        int chunk = gnt >> 5, nt = gnt & 31;
        int dest = ((chunk * 16 + (nt >> 1)) * 16 + kt) * 64 + lane * 2 + (nt & 1);
        d_WGhi[dest] = H;
    } else if (id < 106496) {              // W1: [128,256] (hi only)
        int j = id - 98304;
        int lane = j & 31, kt = (j >> 5) & 15, nt = j >> 9;
        const float* src = w1 + (nt * 8 + (lane >> 2)) * 256;
        int k0 = kt * 16 + (lane & 3) * 2;
        uint2 H;
        unsigned dummy;
        H.x = packsplit(src[k0],   src[k0+1], dummy);
        H.y = packsplit(src[k0+8], src[k0+9], dummy);
        d_W1hi[j] = H;
    } else if (id < 110592) {              // W2: [128,128] (hi only)
        int j = id - 106496;
        int lane = j & 31, kt = (j >> 5) & 7, nt = j >> 8;
        const float* src = w2 + (nt * 8 + (lane >> 2)) * 128;
        int k0 = kt * 16 + (lane & 3) * 2;
        uint2 H;
        unsigned dummy;
        H.x = packsplit(src[k0],   src[k0+1], dummy);
        H.y = packsplit(src[k0+8], src[k0+9], dummy);
        d_W2hi[j] = H;
    } else if (id < 111360) {              // Mi = Wi@embed_w, ci = Wi@embed_b + bi
        int n = id - 110592;
        const float* wr = wi + n * 256;
        float m0 = 0.f, m1 = 0.f, cc = 0.f;
        for (int k = 0; k < 256; k++) {
            float v = wr[k];
            m0 += v * ew[2*k]; m1 += v * ew[2*k+1]; cc += v * eb[k];
        }
        d_Mi[2*n] = m0; d_Mi[2*n+1] = m1; d_ci[n] = cc + bi[n];
    }
}

// =======================================================================
// Persistent fused kernel (r10 base): CTA = 64 rows (agent, rz-half),
// 256 threads. h fragments in SMEM for all 20 steps. eps decoded in-kernel.
// =======================================================================
extern __shared__ unsigned smem_u[];
__global__ void __launch_bounds__(256, 1) k_all(const float* __restrict__ inp,
                                                const float* __restrict__ bh,
                                                const float* __restrict__ bi,
                                                const float* __restrict__ b1,
                                                const float* __restrict__ b2,
                                                const float* __restrict__ w3,
                                                const float* __restrict__ b3,
                                                const unsigned char* __restrict__ eps,
                                                float* __restrict__ out) {
    uint4* hbuf = (uint4*)smem_u;            // 2 buffers x 4096 uint4 (hi 2048 | lo 2048)
    unsigned* fcmem = smem_u + 32768;        // 34048 bytes
    __shared__ int s_ones, s_nz, s_mode;

    int am = blockIdx.x >> 1, rz = blockIdx.x & 1;
    int tid = threadIdx.x;
    int lane = tid & 31, w = tid >> 5;
    int wm = w & 1, wn = w >> 1;
    int lane4 = lane >> 2;
    const uint4* WG4 = (const uint4*)d_WGhi;

    // h(0) = 0 + eps mode detection (each CTA independently)
    if (tid == 0) { s_ones = 0; s_nz = 0; }
    for (int i = tid; i < 4096; i += 256) hbuf[i] = make_uint4(0, 0, 0, 0);
    __syncthreads();
    for (int i = tid; i < 768; i += 256) {
        unsigned char b = eps[i];
        if ((i & 3) == 3 && b == 0x3f) atomicAdd(&s_ones, 1);
        if ((i & 3) != 0 && b != 0) atomicAdd(&s_nz, 1);
    }
    __syncthreads();
    if (tid == 0) s_mode = (s_ones > 0) ? 2 : (s_nz == 0 ? 1 : 0);
    __syncthreads();
    int mode = s_mode;

    int curb = 0;
    int lmt0 = wm * 2;
    int a0 = (lmt0 * 16) * 32 + lane;
    int a1 = a0 + 512;

    for (int t = 0; t < 20; t++) {
        bool full = false;
        if (t >= 8) {
            int m = (t - 8) * 64 + am;
            float v = (mode == 2) ? ((const float*)eps)[m]
                    : (mode == 1) ? (float)((const int*)eps)[m]
                    : (float)eps[m];
            full = (v != 0.f);
        }
        const uint4* Ahi = hbuf + curb * 4096;
        const uint4* Alo = Ahi + 2048;
        unsigned* Whi = (unsigned*)(hbuf + (curb ^ 1) * 4096);
        unsigned* Wlo = Whi + 8192;
        const unsigned* RdHi = (const unsigned*)Ahi;
        const unsigned* RdLo = (const unsigned*)Alo;

        int chkR = full ? 3 : 0;
        int chkZ = full ? 4 : 1;

        for (int cg = 0; cg < 4; cg++) {
            int ntp = cg * 4 + wn;
            int bR = ((chkR * 16 + ntp) * 16) * 32 + lane;
            int bZ = ((chkZ * 16 + ntp) * 16) * 32 + lane;
            int bN = ((2    * 16 + ntp) * 16) * 32 + lane;
            int bI = ((5    * 16 + ntp) * 16) * 32 + lane;

            float acc[2][2][4][4];
#pragma unroll
            for (int i = 0; i < 2; i++)
#pragma unroll
                for (int n = 0; n < 2; n++)
#pragma unroll
                    for (int g = 0; g < 4; g++)
#pragma unroll
                        for (int q = 0; q < 4; q++) acc[i][n][g][q] = 0.f;

            uint4 ahC0 = Ahi[a0], ahC1 = Ahi[a1];
            uint4 alC0 = Alo[a0], alC1 = Alo[a1];
            uint4 WRc = WG4[bR], WZc = WG4[bZ], WNc = WG4[bN];
            uint4 WIc;
            if (full) WIc = WG4[bI];

#pragma unroll 4
            for (int kt = 0; kt < 16; kt++) {
                int on = ((kt + 1 < 16) ? (kt + 1) : 15) * 32;
                uint4 WRn = WG4[bR + on], WZn = WG4[bZ + on], WNn = WG4[bN + on];
                uint4 WIn;
                if (full) WIn = WG4[bI + on];
                uint4 ahN0 = Ahi[a0 + on], ahN1 = Ahi[a1 + on];
                uint4 alN0 = Alo[a0 + on], alN1 = Alo[a1 + on];

                uint2 Br0 = make_uint2(WRc.x, WRc.y), Br1 = make_uint2(WRc.z, WRc.w);
                uint2 Bz0 = make_uint2(WZc.x, WZc.y), Bz1 = make_uint2(WZc.z, WZc.w);
                uint2 Bn0 = make_uint2(WNc.x, WNc.y), Bn1 = make_uint2(WNc.z, WNc.w);

                mma16816(acc[0][0][0], ahC0, Br0); mma16816(acc[1][0][0], ahC1, Br0);
                mma16816(acc[0][1][0], ahC0, Br1); mma16816(acc[1][1][0], ahC1, Br1);
                mma16816(acc[0][0][1], ahC0, Bz0); mma16816(acc[1][0][1], ahC1, Bz0);
                mma16816(acc[0][1][1], ahC0, Bz1); mma16816(acc[1][1][1], ahC1, Bz1);
                mma16816(acc[0][0][2], ahC0, Bn0); mma16816(acc[1][0][2], ahC1, Bn0);
                mma16816(acc[0][1][2], ahC0, Bn1); mma16816(acc[1][1][2], ahC1, Bn1);
                mma16816(acc[0][0][2], alC0, Bn0); mma16816(acc[1][0][2], alC1, Bn0);
                mma16816(acc[0][1][2], alC0, Bn1); mma16816(acc[1][1][2], alC1, Bn1);
                if (full) {
                    uint2 Bi0 = make_uint2(WIc.x, WIc.y), Bi1 = make_uint2(WIc.z, WIc.w);
                    mma16816(acc[0][0][3], ahC0, Bi0); mma16816(acc[1][0][3], ahC1, Bi0);
                    mma16816(acc[0][1][3], ahC0, Bi1); mma16816(acc[1][1][3], ahC1, Bi1);
                    mma16816(acc[0][0][3], alC0, Bi0); mma16816(acc[1][0][3], alC1, Bi0);
                    mma16816(acc[0][1][3], alC0, Bi1); mma16816(acc[1][1][3], alC1, Bi1);
                    WIc = WIn;
                }
                ahC0 = ahN0; ahC1 = ahN1; alC0 = alN0; alC1 = alN1;
                WRc = WRn; WZc = WZn; WNc = WNn;
            }

            // ---- gate epilogue ----
            int nt0 = cg * 8 + wn * 2;
            float bhr0[2], bhr1[2], bhz0[2], bhz1[2], bhn0[2], bhn1[2];
            float bir0[2], bir1[2], biz0[2], biz1[2], bin0[2], bin1[2];
            float M0a[2][3], M0b[2][3], M1a[2][3], M1b[2][3], C0[2][3], C1[2][3];
            int cc[2];
#pragma unroll
            for (int n = 0; n < 2; n++) {
                int c = (nt0 + n) * 8 + (lane & 3) * 2;
                cc[n] = c;
                bhr0[n] = bh[c];       bhr1[n] = bh[c + 1];
                bhz0[n] = bh[256 + c]; bhz1[n] = bh[257 + c];
                bhn0[n] = bh[512 + c]; bhn1[n] = bh[513 + c];
                if (full) {
                    bir0[n] = bi[c];       bir1[n] = bi[c + 1];
                    biz0[n] = bi[256 + c]; biz1[n] = bi[257 + c];
                    bin0[n] = bi[512 + c]; bin1[n] = bi[513 + c];
                } else {
#pragma unroll
                    for (int g = 0; g < 3; g++) {
                        int n0 = g * 256 + c;
                        M0a[n][g] = d_Mi[2*n0];     M0b[n][g] = d_Mi[2*n0 + 1];   C0[n][g] = d_ci[n0];
                        M1a[n][g] = d_Mi[2*n0 + 2]; M1b[n][g] = d_Mi[2*n0 + 3];   C1[n][g] = d_ci[n0 + 1];
                    }
                }
            }

#pragma unroll
            for (int i = 0; i < 2; i++) {
#pragma unroll
                for (int half = 0; half < 2; half++) {
                    int rloc = (lmt0 + i) * 16 + half * 8 + lane4;
                    int q0 = half * 2;
                    float x0 = 0.f, x1 = 0.f;
                    if (!full) {
                        int b = rz * 64 + rloc;
                        const float* ip = inp + ((b * 64 + am) * 20 + t) * 2;
                        x0 = ip[0]; x1 = ip[1];
                    }
#pragma unroll
                    for (int n = 0; n < 2; n++) {
                        int c = cc[n];
                        int widx = fidx(rloc, c, 16);
                        unsigned uh = RdHi[widx], ul = RdLo[widx];
                        __half2 hh = *(__half2*)&uh, hl = *(__half2*)&ul;
                        float hox = __half2float(__low2half(hh))  + __half2float(__low2half(hl));
                        float hoy = __half2float(__high2half(hh)) + __half2float(__high2half(hl));
                        float r0g, r1g, z0g, z1g, n0g, n1g;
                        if (full) {
                            r0g = sigf(acc[i][n][0][q0]   + bir0[n] + bhr0[n]);
                            r1g = sigf(acc[i][n][0][q0+1] + bir1[n] + bhr1[n]);
                            z0g = sigf(acc[i][n][1][q0]   + biz0[n] + bhz0[n]);
                            z1g = sigf(acc[i][n][1][q0+1] + biz1[n] + bhz1[n]);
                            n0g = tanh_f(acc[i][n][3][q0]   + bin0[n] + r0g * (acc[i][n][2][q0]   + bhn0[n]));
                            n1g = tanh_f(acc[i][n][3][q0+1] + bin1[n] + r1g * (acc[i][n][2][q0+1] + bhn1[n]));
                        } else {
                            float ir0 = x0 * M0a[n][0] + x1 * M0b[n][0] + C0[n][0];
                            float iz0 = x0 * M0a[n][1] + x1 * M0b[n][1] + C0[n][1];
                            float in0 = x0 * M0a[n][2] + x1 * M0b[n][2] + C0[n][2];
                            float ir1 = x0 * M1a[n][0] + x1 * M1b[n][0] + C1[n][0];
                            float iz1 = x0 * M1a[n][1] + x1 * M1b[n][1] + C1[n][1];
                            float in1 = x0 * M1a[n][2] + x1 * M1b[n][2] + C1[n][2];
                            r0g = sigf(ir0 + acc[i][n][0][q0]   + bhr0[n]);
                            r1g = sigf(ir1 + acc[i][n][0][q0+1] + bhr1[n]);
                            z0g = sigf(iz0 + acc[i][n][1][q0]   + bhz0[n]);
                            z1g = sigf(iz1 + acc[i][n][1][q0+1] + bhz1[n]);
                            n0g = tanh_f(in0 + r0g * (acc[i][n][2][q0]   + bhn0[n]));
                            n1g = tanh_f(in1 + r1g * (acc[i][n][2][q0+1] + bhn1[n]));
                        }
                        float h0 = (1.f - z0g) * n0g + z0g * hox;
                        float h1 = (1.f - z1g) * n1g + z1g * hoy;
                        unsigned lo, hi = packsplit(h0, h1, lo);
                        Whi[widx] = hi; Wlo[widx] = lo;
                    }
                }
            }
        }
        __syncthreads();
        curb ^= 1;

        // ================= inline FC head (t >= 8), fc weights 2-term =================
        if (t >= 8) {
            const uint4* Fhi = hbuf + curb * 4096;
            const uint4* Flo = Fhi + 2048;
            unsigned* sY1hi = fcmem;
            unsigned* sY1lo = fcmem + 4096;
            float* sy2 = (float*)fcmem;

            // ---- fc1 (2-term: ah*Bh + al*Bh) ----
            float fa[2][4][4];
#pragma unroll
            for (int i = 0; i < 2; i++)
#pragma unroll
                for (int j = 0; j < 4; j++)
#pragma unroll
                    for (int q = 0; q < 4; q++) fa[i][j][q] = 0.f;
#pragma unroll 2
            for (int kt = 0; kt < 16; kt++) {
                uint4 ah[2], al[2];
#pragma unroll
                for (int i = 0; i < 2; i++) {
                    int base = ((lmt0 + i) * 16 + kt) * 32 + lane;
                    ah[i] = Fhi[base];
                    al[i] = Flo[base];
                }
#pragma unroll
                for (int j = 0; j < 4; j++) {
                    int bb = ((wn * 4 + j) * 16 + kt) * 32 + lane;
                    uint2 Bh = d_W1hi[bb];
#pragma unroll
                    for (int i = 0; i < 2; i++) {
                        mma16816(fa[i][j], ah[i], Bh);
                        mma16816(fa[i][j], al[i], Bh);
                    }
                }
            }
#pragma unroll
            for (int i = 0; i < 2; i++)
#pragma unroll
                for (int j = 0; j < 4; j++) {
                    int rr = wm * 32 + i * 16 + lane4;
                    int cf = wn * 32 + j * 8 + (lane & 3) * 2;
                    float bb0 = b1[cf], bb1 = b1[cf + 1];
                    float v0 = eluf(fa[i][j][0] + bb0);
                    float v1 = eluf(fa[i][j][1] + bb1);
                    unsigned lo, hi = packsplit(v0, v1, lo);
                    int widx = fidx(rr, cf, 8);
                    sY1hi[widx] = hi; sY1lo[widx] = lo;
                    v0 = eluf(fa[i][j][2] + bb0);
                    v1 = eluf(fa[i][j][3] + bb1);
                    hi = packsplit(v0, v1, lo);
                    widx = fidx(rr + 8, cf, 8);
                    sY1hi[widx] = hi; sY1lo[widx] = lo;
                }
            __syncthreads();

            // ---- fc2 (2-term) ----
            float fb[2][4][4];
#pragma unroll
            for (int i = 0; i < 2; i++)
#pragma unroll
                for (int j = 0; j < 4; j++)
#pragma unroll
                    for (int q = 0; q < 4; q++) fb[i][j][q] = 0.f;
            const uint4* sY1hi4 = (const uint4*)sY1hi;
            const uint4* sY1lo4 = (const uint4*)sY1lo;
#pragma unroll 2
            for (int kt = 0; kt < 8; kt++) {
                uint4 ah[2], al[2];
#pragma unroll
                for (int i = 0; i < 2; i++) {
                    int base = ((wm * 2 + i) * 8 + kt) * 32 + lane;
                    ah[i] = sY1hi4[base];
                    al[i] = sY1lo4[base];
                }
#pragma unroll
                for (int j = 0; j < 4; j++) {
                    int bb = ((wn * 4 + j) * 8 + kt) * 32 + lane;
                    uint2 Bh = d_W2hi[bb];
#pragma unroll
                    for (int i = 0; i < 2; i++) {
                        mma16816(fb[i][j], ah[i], Bh);
                        mma16816(fb[i][j], al[i], Bh);
                    }
                }
            }
            __syncthreads();

#pragma unroll
            for (int i = 0; i < 2; i++)
#pragma unroll
                for (int j = 0; j < 4; j++) {
                    int rr = wm * 32 + i * 16 + lane4;
                    int cf = wn * 32 + j * 8 + (lane & 3) * 2;
                    float bb0 = b2[cf], bb1 = b2[cf + 1];
                    sy2[rr * 132 + cf]           = eluf(fb[i][j][0] + bb0);
                    sy2[rr * 132 + cf + 1]       = eluf(fb[i][j][1] + bb1);
                    sy2[(rr + 8) * 132 + cf]     = eluf(fb[i][j][2] + bb0);
                    sy2[(rr + 8) * 132 + cf + 1] = eluf(fb[i][j][3] + bb1);
                }
            __syncthreads();

            // ---- fc3 + gt mask ----
            if (tid < 128) {
                int rl = tid >> 1, cr = tid & 1;
                const float* wr = w3 + cr * 128;
                float s = b3[cr];
#pragma unroll 8
                for (int k = 0; k < 128; k++) s += sy2[rl * 132 + k] * __ldg(wr + k);
                int b = rz * 64 + rl;
                float gv = inp[((b * 64 + am) * 20 + t) * 2 + cr];
                out[((b * 64 + am) * 12 + (t - 8)) * 2 + cr] = (gv != 0.f) ? s : 0.f;
            }
            __syncthreads();
        }
    }
}

extern "C" void kernel_launch(void* const* d_in, const int* in_sizes, int n_in,
                              void* d_out, int out_size) {
    int sh = (n_in >= 15 && in_sizes[1] <= 4) ? 0 : -1;
    const float* inputs = (const float*)d_in[0];
    const unsigned char* eps = (const unsigned char*)d_in[2 + sh];
    const float* ew = (const float*)d_in[3 + sh];
    const float* eb = (const float*)d_in[4 + sh];
    const float* wi = (const float*)d_in[5 + sh];
    const float* wh = (const float*)d_in[6 + sh];
    const float* bi = (const float*)d_in[7 + sh];
    const float* bh = (const float*)d_in[8 + sh];
    const float* w1 = (const float*)d_in[9 + sh];
    const float* b1 = (const float*)d_in[10 + sh];
    const float* w2 = (const float*)d_in[11 + sh];
    const float* b2 = (const float*)d_in[12 + sh];
    const float* w3 = (const float*)d_in[13 + sh];
    const float* b3 = (const float*)d_in[14 + sh];
    float* out = (float*)d_out;

    static int smem_set = 0;
    if (!smem_set) {
        cudaFuncSetAttribute(k_all, cudaFuncAttributeMaxDynamicSharedMemorySize, 165120);
        smem_set = 1;
    }

    s_pack<<<435, 256>>>(wh, wi, w1, w2, ew, eb, bi);
    k_all<<<128, 256, 165120>>>(inputs, bh, bi, b1, b2, w3, b3, eps, out);
}

// round 15
// speedup vs baseline: 1.0477x; 1.0038x over previous
#include <cuda_runtime.h>
#include <cuda_fp16.h>

// ---- static device scratch ----
__device__ uint2 d_WGhi[192*16*32];   // GRU B frags, paired-nt interleaved
__device__ uint2 d_W1hi[16*16*32];
__device__ uint2 d_W2hi[16*8*32];
__device__ float d_Mi[768*2];
__device__ float d_ci[768];

// ---- helpers ----
__device__ __forceinline__ unsigned packsplit(float v0, float v1, unsigned &lo) {
    __half h0 = __float2half(v0);
    __half h1 = __float2half(v1);
    __half l0 = __float2half(v0 - __half2float(h0));
    __half l1 = __float2half(v1 - __half2float(h1));
    lo = ((unsigned)__half_as_ushort(l1) << 16) | (unsigned)__half_as_ushort(l0);
    return ((unsigned)__half_as_ushort(h1) << 16) | (unsigned)__half_as_ushort(h0);
}
__device__ __forceinline__ int fidx(int r, int c, int KT) {
    return (((r >> 4) * KT + (c >> 4)) * 32 + (r & 7) * 4 + ((c & 7) >> 1)) * 4
           + ((r >> 3) & 1) + (((c >> 3) & 1) << 1);
}
__device__ __forceinline__ void mma16816(float (&c)[4], const uint4 a, const uint2 b) {
    asm volatile(
        "mma.sync.aligned.m16n8k16.row.col.f32.f16.f16.f32 "
        "{%0,%1,%2,%3},{%4,%5,%6,%7},{%8,%9},{%0,%1,%2,%3};\n"
        : "+f"(c[0]), "+f"(c[1]), "+f"(c[2]), "+f"(c[3])
        : "r"(a.x), "r"(a.y), "r"(a.z), "r"(a.w), "r"(b.x), "r"(b.y));
}
__device__ __forceinline__ float sigf(float x) { return __fdividef(1.f, 1.f + __expf(-x)); }
__device__ __forceinline__ float tanh_f(float x) { return 2.f * sigf(2.f * x) - 1.f; }
__device__ __forceinline__ float eluf(float x) { return x > 0.f ? x : (__expf(x) - 1.f); }

// ---- setup: pack weights ----
__global__ void s_pack(const float* __restrict__ wh, const float* __restrict__ wi,
                       const float* __restrict__ w1, const float* __restrict__ w2,
                       const float* __restrict__ ew, const float* __restrict__ eb,
                       const float* __restrict__ bi) {
    int id = blockIdx.x * 256 + threadIdx.x;
    if (id < 98304) {
        // WG chunk layout: [0,768): Wh r,z,n; [768,1280): Wi+Wh r,z; [1280,1536): Wi n
        int lane = id & 31, kt = (id >> 5) & 15, gnt = id >> 9;
        int n = gnt * 8 + (lane >> 2);
        const float* sa;
        const float* sb = 0;
        if (n < 768)        { sa = wh + n * 256; }
        else if (n < 1280)  { sa = wi + (n - 768) * 256; sb = wh + (n - 768) * 256; }
        else                { sa = wi + (n - 1280 + 512) * 256; }
        int k0 = kt * 16 + (lane & 3) * 2;
        float v0 = sa[k0]     + (sb ? sb[k0]     : 0.f);
        float v1 = sa[k0+1]   + (sb ? sb[k0+1]   : 0.f);
        float v2 = sa[k0+8]   + (sb ? sb[k0+8]   : 0.f);
        float v3 = sa[k0+9]   + (sb ? sb[k0+9]   : 0.f);
        uint2 H;
        unsigned dummy;
        H.x = packsplit(v0, v1, dummy);
        H.y = packsplit(v2, v3, dummy);
        int chunk = gnt >> 5, nt = gnt & 31;
        int dest = ((chunk * 16 + (nt >> 1)) * 16 + kt) * 64 + lane * 2 + (nt & 1);
        d_WGhi[dest] = H;
    } else if (id < 106496) {              // W1 (hi only)
        int j = id - 98304;
        int lane = j & 31, kt = (j >> 5) & 15, nt = j >> 9;
        const float* src = w1 + (nt * 8 + (lane >> 2)) * 256;
        int k0 = kt * 16 + (lane & 3) * 2;
        uint2 H;
        unsigned dummy;
        H.x = packsplit(src[k0],   src[k0+1], dummy);
        H.y = packsplit(src[k0+8], src[k0+9], dummy);
        d_W1hi[j] = H;
    } else if (id < 110592) {              // W2 (hi only)
        int j = id - 106496;
        int lane = j & 31, kt = (j >> 5) & 7, nt = j >> 8;
        const float* src = w2 + (nt * 8 + (lane >> 2)) * 128;
        int k0 = kt * 16 + (lane & 3) * 2;
        uint2 H;
        unsigned dummy;
        H.x = packsplit(src[k0],   src[k0+1], dummy);
        H.y = packsplit(src[k0+8], src[k0+9], dummy);
        d_W2hi[j] = H;
    } else if (id < 111360) {              // Mi = Wi@embed_w, ci = Wi@embed_b + bi
        int n = id - 110592;
        const float* wr = wi + n * 256;
        float m0 = 0.f, m1 = 0.f, cc = 0.f;
        for (int k = 0; k < 256; k++) {
            float v = wr[k];
            m0 += v * ew[2*k]; m1 += v * ew[2*k+1]; cc += v * eb[k];
        }
        d_Mi[2*n] = m0; d_Mi[2*n+1] = m1; d_ci[n] = cc + bi[n];
    }
}

// =======================================================================
// Persistent fused kernel: CTA = 64 rows (agent, rz-half), 256 threads.
// FC(t-1) overlapped into GRU(t): both only READ h(curb); fc1 runs before
// the first barrier so its mma fill other warps' GRU stall slots.
// =======================================================================
extern __shared__ unsigned smem_u[];
__global__ void __launch_bounds__(256, 1) k_all(const float* __restrict__ inp,
                                                const float* __restrict__ bh,
                                                const float* __restrict__ bi,
                                                const float* __restrict__ b1,
                                                const float* __restrict__ b2,
                                                const float* __restrict__ w3,
                                                const float* __restrict__ b3,
                                                const unsigned char* __restrict__ eps,
                                                float* __restrict__ out) {
    uint4* hbuf = (uint4*)smem_u;            // 2 buffers x 4096 uint4 (hi 2048 | lo 2048)
    unsigned* fcmem = smem_u + 32768;        // 34048 bytes
    __shared__ int s_ones, s_nz, s_mode;

    int am = blockIdx.x >> 1, rz = blockIdx.x & 1;
    int tid = threadIdx.x;
    int lane = tid & 31, w = tid >> 5;
    int wm = w & 1, wn = w >> 1;
    int lane4 = lane >> 2;
    const uint4* WG4 = (const uint4*)d_WGhi;

    if (tid == 0) { s_ones = 0; s_nz = 0; }
    for (int i = tid; i < 4096; i += 256) hbuf[i] = make_uint4(0, 0, 0, 0);
    __syncthreads();
    for (int i = tid; i < 768; i += 256) {
        unsigned char b = eps[i];
        if ((i & 3) == 3 && b == 0x3f) atomicAdd(&s_ones, 1);
        if ((i & 3) != 0 && b != 0) atomicAdd(&s_nz, 1);
    }
    __syncthreads();
    if (tid == 0) s_mode = (s_ones > 0) ? 2 : (s_nz == 0 ? 1 : 0);
    __syncthreads();
    int mode = s_mode;

    int curb = 0;
    int lmt0 = wm * 2;
    int a0 = (lmt0 * 16) * 32 + lane;
    int a1 = a0 + 512;

    for (int t = 0; t <= 20; t++) {
        // =================== GRU step t (t < 20) ===================
        if (t < 20) {
            bool full = false;
            if (t >= 8) {
                int m = (t - 8) * 64 + am;
                float v = (mode == 2) ? ((const float*)eps)[m]
                        : (mode == 1) ? (float)((const int*)eps)[m]
                        : (float)eps[m];
                full = (v != 0.f);
            }
            const uint4* Ahi = hbuf + curb * 4096;
            const uint4* Alo = Ahi + 2048;
            unsigned* Whi = (unsigned*)(hbuf + (curb ^ 1) * 4096);
            unsigned* Wlo = Whi + 8192;
            const unsigned* RdHi = (const unsigned*)Ahi;
            const unsigned* RdLo = (const unsigned*)Alo;

            int chkR = full ? 3 : 0;
            int chkZ = full ? 4 : 1;

            for (int cg = 0; cg < 4; cg++) {
                int ntp = cg * 4 + wn;
                int bR = ((chkR * 16 + ntp) * 16) * 32 + lane;
                int bZ = ((chkZ * 16 + ntp) * 16) * 32 + lane;
                int bN = ((2    * 16 + ntp) * 16) * 32 + lane;
                int bI = ((5    * 16 + ntp) * 16) * 32 + lane;

                float acc[2][2][4][4];
#pragma unroll
                for (int i = 0; i < 2; i++)
#pragma unroll
                    for (int n = 0; n < 2; n++)
#pragma unroll
                        for (int g = 0; g < 4; g++)
#pragma unroll
                            for (int q = 0; q < 4; q++) acc[i][n][g][q] = 0.f;

                uint4 ahC0 = Ahi[a0], ahC1 = Ahi[a1];
                uint4 alC0 = Alo[a0], alC1 = Alo[a1];
                uint4 WRc = WG4[bR], WZc = WG4[bZ], WNc = WG4[bN];
                uint4 WIc;
                if (full) WIc = WG4[bI];

#pragma unroll 4
                for (int kt = 0; kt < 16; kt++) {
                    int on = ((kt + 1 < 16) ? (kt + 1) : 15) * 32;
                    uint4 WRn = WG4[bR + on], WZn = WG4[bZ + on], WNn = WG4[bN + on];
                    uint4 WIn;
                    if (full) WIn = WG4[bI + on];
                    uint4 ahN0 = Ahi[a0 + on], ahN1 = Ahi[a1 + on];
                    uint4 alN0 = Alo[a0 + on], alN1 = Alo[a1 + on];

                    uint2 Br0 = make_uint2(WRc.x, WRc.y), Br1 = make_uint2(WRc.z, WRc.w);
                    uint2 Bz0 = make_uint2(WZc.x, WZc.y), Bz1 = make_uint2(WZc.z, WZc.w);
                    uint2 Bn0 = make_uint2(WNc.x, WNc.y), Bn1 = make_uint2(WNc.z, WNc.w);

                    mma16816(acc[0][0][0], ahC0, Br0); mma16816(acc[1][0][0], ahC1, Br0);
                    mma16816(acc[0][1][0], ahC0, Br1); mma16816(acc[1][1][0], ahC1, Br1);
                    mma16816(acc[0][0][1], ahC0, Bz0); mma16816(acc[1][0][1], ahC1, Bz0);
                    mma16816(acc[0][1][1], ahC0, Bz1); mma16816(acc[1][1][1], ahC1, Bz1);
                    mma16816(acc[0][0][2], ahC0, Bn0); mma16816(acc[1][0][2], ahC1, Bn0);
                    mma16816(acc[0][1][2], ahC0, Bn1); mma16816(acc[1][1][2], ahC1, Bn1);
                    mma16816(acc[0][0][2], alC0, Bn0); mma16816(acc[1][0][2], alC1, Bn0);
                    mma16816(acc[0][1][2], alC0, Bn1); mma16816(acc[1][1][2], alC1, Bn1);
                    if (full) {
                        uint2 Bi0 = make_uint2(WIc.x, WIc.y), Bi1 = make_uint2(WIc.z, WIc.w);
                        mma16816(acc[0][0][3], ahC0, Bi0); mma16816(acc[1][0][3], ahC1, Bi0);
                        mma16816(acc[0][1][3], ahC0, Bi1); mma16816(acc[1][1][3], ahC1, Bi1);
                        mma16816(acc[0][0][3], alC0, Bi0); mma16816(acc[1][0][3], alC1, Bi0);
                        mma16816(acc[0][1][3], alC0, Bi1); mma16816(acc[1][1][3], alC1, Bi1);
                        WIc = WIn;
                    }
                    ahC0 = ahN0; ahC1 = ahN1; alC0 = alN0; alC1 = alN1;
                    WRc = WRn; WZc = WZn; WNc = WNn;
                }

                // ---- gate epilogue ----
                int nt0 = cg * 8 + wn * 2;
                float bhr0[2], bhr1[2], bhz0[2], bhz1[2], bhn0[2], bhn1[2];
                float bir0[2], bir1[2], biz0[2], biz1[2], bin0[2], bin1[2];
                float M0a[2][3], M0b[2][3], M1a[2][3], M1b[2][3], C0[2][3], C1[2][3];
                int cc[2];
#pragma unroll
                for (int n = 0; n < 2; n++) {
                    int c = (nt0 + n) * 8 + (lane & 3) * 2;
                    cc[n] = c;
                    bhr0[n] = bh[c];       bhr1[n] = bh[c + 1];
                    bhz0[n] = bh[256 + c]; bhz1[n] = bh[257 + c];
                    bhn0[n] = bh[512 + c]; bhn1[n] = bh[513 + c];
                    if (full) {
                        bir0[n] = bi[c];       bir1[n] = bi[c + 1];
                        biz0[n] = bi[256 + c]; biz1[n] = bi[257 + c];
                        bin0[n] = bi[512 + c]; bin1[n] = bi[513 + c];
                    } else {
#pragma unroll
                        for (int g = 0; g < 3; g++) {
                            int n0 = g * 256 + c;
                            M0a[n][g] = d_Mi[2*n0];     M0b[n][g] = d_Mi[2*n0 + 1];   C0[n][g] = d_ci[n0];
                            M1a[n][g] = d_Mi[2*n0 + 2]; M1b[n][g] = d_Mi[2*n0 + 3];   C1[n][g] = d_ci[n0 + 1];
                        }
                    }
                }

#pragma unroll
                for (int i = 0; i < 2; i++) {
#pragma unroll
                    for (int half = 0; half < 2; half++) {
                        int rloc = (lmt0 + i) * 16 + half * 8 + lane4;
                        int q0 = half * 2;
                        float x0 = 0.f, x1 = 0.f;
                        if (!full) {
                            int b = rz * 64 + rloc;
                            const float* ip = inp + ((b * 64 + am) * 20 + t) * 2;
                            x0 = ip[0]; x1 = ip[1];
                        }
#pragma unroll
                        for (int n = 0; n < 2; n++) {
                            int c = cc[n];
                            int widx = fidx(rloc, c, 16);
                            unsigned uh = RdHi[widx], ul = RdLo[widx];
                            __half2 hh = *(__half2*)&uh, hl = *(__half2*)&ul;
                            float hox = __half2float(__low2half(hh))  + __half2float(__low2half(hl));
                            float hoy = __half2float(__high2half(hh)) + __half2float(__high2half(hl));
                            float r0g, r1g, z0g, z1g, n0g, n1g;
                            if (full) {
                                r0g = sigf(acc[i][n][0][q0]   + bir0[n] + bhr0[n]);
                                r1g = sigf(acc[i][n][0][q0+1] + bir1[n] + bhr1[n]);
                                z0g = sigf(acc[i][n][1][q0]   + biz0[n] + bhz0[n]);
                                z1g = sigf(acc[i][n][1][q0+1] + biz1[n] + bhz1[n]);
                                n0g = tanh_f(acc[i][n][3][q0]   + bin0[n] + r0g * (acc[i][n][2][q0]   + bhn0[n]));
                                n1g = tanh_f(acc[i][n][3][q0+1] + bin1[n] + r1g * (acc[i][n][2][q0+1] + bhn1[n]));
                            } else {
                                float ir0 = x0 * M0a[n][0] + x1 * M0b[n][0] + C0[n][0];
                                float iz0 = x0 * M0a[n][1] + x1 * M0b[n][1] + C0[n][1];
                                float in0 = x0 * M0a[n][2] + x1 * M0b[n][2] + C0[n][2];
                                float ir1 = x0 * M1a[n][0] + x1 * M1b[n][0] + C1[n][0];
                                float iz1 = x0 * M1a[n][1] + x1 * M1b[n][1] + C1[n][1];
                                float in1 = x0 * M1a[n][2] + x1 * M1b[n][2] + C1[n][2];
                                r0g = sigf(ir0 + acc[i][n][0][q0]   + bhr0[n]);
                                r1g = sigf(ir1 + acc[i][n][0][q0+1] + bhr1[n]);
                                z0g = sigf(iz0 + acc[i][n][1][q0]   + bhz0[n]);
                                z1g = sigf(iz1 + acc[i][n][1][q0+1] + bhz1[n]);
                                n0g = tanh_f(in0 + r0g * (acc[i][n][2][q0]   + bhn0[n]));
                                n1g = tanh_f(in1 + r1g * (acc[i][n][2][q0+1] + bhn1[n]));
                            }
                            float h0 = (1.f - z0g) * n0g + z0g * hox;
                            float h1 = (1.f - z1g) * n1g + z1g * hoy;
                            unsigned lo, hi = packsplit(h0, h1, lo);
                            Whi[widx] = hi; Wlo[widx] = lo;
                        }
                    }
                }
            }
        }

        // =========== FC head for pred step p = t-1 (overlapped) ===========
        if (t >= 9) {
            int p = t - 1;
            const uint4* Fhi = hbuf + curb * 4096;   // h(p+1) = h(t)
            const uint4* Flo = Fhi + 2048;
            unsigned* sY1hi = fcmem;
            unsigned* sY1lo = fcmem + 4096;
            float* sy2 = (float*)fcmem;

            // ---- fc1 (2-term), runs concurrently with other warps' GRU ----
            float fa[2][4][4];
#pragma unroll
            for (int i = 0; i < 2; i++)
#pragma unroll
                for (int j = 0; j < 4; j++)
#pragma unroll
                    for (int q = 0; q < 4; q++) fa[i][j][q] = 0.f;
#pragma unroll 2
            for (int kt = 0; kt < 16; kt++) {
                uint4 ah[2], al[2];
#pragma unroll
                for (int i = 0; i < 2; i++) {
                    int base = ((lmt0 + i) * 16 + kt) * 32 + lane;
                    ah[i] = Fhi[base];
                    al[i] = Flo[base];
                }
#pragma unroll
                for (int j = 0; j < 4; j++) {
                    int bb = ((wn * 4 + j) * 16 + kt) * 32 + lane;
                    uint2 Bh = d_W1hi[bb];
#pragma unroll
                    for (int i = 0; i < 2; i++) {
                        mma16816(fa[i][j], ah[i], Bh);
                        mma16816(fa[i][j], al[i], Bh);
                    }
                }
            }
#pragma unroll
            for (int i = 0; i < 2; i++)
#pragma unroll
                for (int j = 0; j < 4; j++) {
                    int rr = wm * 32 + i * 16 + lane4;
                    int cf = wn * 32 + j * 8 + (lane & 3) * 2;
                    float bb0 = b1[cf], bb1 = b1[cf + 1];
                    float v0 = eluf(fa[i][j][0] + bb0);
                    float v1 = eluf(fa[i][j][1] + bb1);
                    unsigned lo, hi = packsplit(v0, v1, lo);
                    int widx = fidx(rr, cf, 8);
                    sY1hi[widx] = hi; sY1lo[widx] = lo;
                    v0 = eluf(fa[i][j][2] + bb0);
                    v1 = eluf(fa[i][j][3] + bb1);
                    hi = packsplit(v0, v1, lo);
                    widx = fidx(rr + 8, cf, 8);
                    sY1hi[widx] = hi; sY1lo[widx] = lo;
                }
            __syncthreads();

            // ---- fc2 (2-term) ----
            float fb[2][4][4];
#pragma unroll
            for (int i = 0; i < 2; i++)
#pragma unroll
                for (int j = 0; j < 4; j++)
#pragma unroll
                    for (int q = 0; q < 4; q++) fb[i][j][q] = 0.f;
            const uint4* sY1hi4 = (const uint4*)sY1hi;
            const uint4* sY1lo4 = (const uint4*)sY1lo;
#pragma unroll 2
            for (int kt = 0; kt < 8; kt++) {
                uint4 ah[2], al[2];
#pragma unroll
                for (int i = 0; i < 2; i++) {
                    int base = ((wm * 2 + i) * 8 + kt) * 32 + lane;
                    ah[i] = sY1hi4[base];
                    al[i] = sY1lo4[base];
                }
#pragma unroll
                for (int j = 0; j < 4; j++) {
                    int bb = ((wn * 4 + j) * 8 + kt) * 32 + lane;
                    uint2 Bh = d_W2hi[bb];
#pragma unroll
                    for (int i = 0; i < 2; i++) {
                        mma16816(fb[i][j], ah[i], Bh);
                        mma16816(fb[i][j], al[i], Bh);
                    }
                }
            }
            __syncthreads();

#pragma unroll
            for (int i = 0; i < 2; i++)
#pragma unroll
                for (int j = 0; j < 4; j++) {
                    int rr = wm * 32 + i * 16 + lane4;
                    int cf = wn * 32 + j * 8 + (lane & 3) * 2;
                    float bb0 = b2[cf], bb1 = b2[cf + 1];
                    sy2[rr * 132 + cf]           = eluf(fb[i][j][0] + bb0);
                    sy2[rr * 132 + cf + 1]       = eluf(fb[i][j][1] + bb1);
                    sy2[(rr + 8) * 132 + cf]     = eluf(fb[i][j][2] + bb0);
                    sy2[(rr + 8) * 132 + cf + 1] = eluf(fb[i][j][3] + bb1);
                }
            __syncthreads();

            // ---- fc3 + gt mask ----
            if (tid < 128) {
                int rl = tid >> 1, cr = tid & 1;
                const float* wr = w3 + cr * 128;
                float s = b3[cr];
#pragma unroll 8
                for (int k = 0; k < 128; k++) s += sy2[rl * 132 + k] * __ldg(wr + k);
                int b = rz * 64 + rl;
                float gv = inp[((b * 64 + am) * 20 + p) * 2 + cr];
                out[((b * 64 + am) * 12 + (p - 8)) * 2 + cr] = (gv != 0.f) ? s : 0.f;
            }
        }

        __syncthreads();
        if (t < 20) curb ^= 1;
    }
}

extern "C" void kernel_launch(void* const* d_in, const int* in_sizes, int n_in,
                              void* d_out, int out_size) {
    int sh = (n_in >= 15 && in_sizes[1] <= 4) ? 0 : -1;
    const float* inputs = (const float*)d_in[0];
    const unsigned char* eps = (const unsigned char*)d_in[2 + sh];
    const float* ew = (const float*)d_in[3 + sh];
    const float* eb = (const float*)d_in[4 + sh];
    const float* wi = (const float*)d_in[5 + sh];
    const float* wh = (const float*)d_in[6 + sh];
    const float* bi = (const float*)d_in[7 + sh];
    const float* bh = (const float*)d_in[8 + sh];
    const float* w1 = (const float*)d_in[9 + sh];
    const float* b1 = (const float*)d_in[10 + sh];
    const float* w2 = (const float*)d_in[11 + sh];
    const float* b2 = (const float*)d_in[12 + sh];
    const float* w3 = (const float*)d_in[13 + sh];
    const float* b3 = (const float*)d_in[14 + sh];
    float* out = (float*)d_out;

    static int smem_set = 0;
    if (!smem_set) {
        cudaFuncSetAttribute(k_all, cudaFuncAttributeMaxDynamicSharedMemorySize, 165120);
        smem_set = 1;
    }

    s_pack<<<435, 256>>>(wh, wi, w1, w2, ew, eb, bi);
    k_all<<<128, 256, 165120>>>(inputs, bh, bi, b1, b2, w3, b3, eps, out);
}

// round 16
// speedup vs baseline: 1.1544x; 1.1019x over previous
#include <cuda_runtime.h>
#include <cuda_fp16.h>

// ---- static device scratch ----
__device__ uint2 d_WGhi[192*16*32];   // GRU B frags, paired-nt interleaved
__device__ uint2 d_W1hi[16*16*32];
__device__ uint2 d_W2hi[16*8*32];
__device__ float d_Mi[768*2];
__device__ float d_ci[768];

// ---- helpers ----
__device__ __forceinline__ unsigned packsplit(float v0, float v1, unsigned &lo) {
    __half h0 = __float2half(v0);
    __half h1 = __float2half(v1);
    __half l0 = __float2half(v0 - __half2float(h0));
    __half l1 = __float2half(v1 - __half2float(h1));
    lo = ((unsigned)__half_as_ushort(l1) << 16) | (unsigned)__half_as_ushort(l0);
    return ((unsigned)__half_as_ushort(h1) << 16) | (unsigned)__half_as_ushort(h0);
}
__device__ __forceinline__ int fidx(int r, int c, int KT) {
    return (((r >> 4) * KT + (c >> 4)) * 32 + (r & 7) * 4 + ((c & 7) >> 1)) * 4
           + ((r >> 3) & 1) + (((c >> 3) & 1) << 1);
}
__device__ __forceinline__ void mma16816(float (&c)[4], const uint4 a, const uint2 b) {
    asm volatile(
        "mma.sync.aligned.m16n8k16.row.col.f32.f16.f16.f32 "
        "{%0,%1,%2,%3},{%4,%5,%6,%7},{%8,%9},{%0,%1,%2,%3};\n"
        : "+f"(c[0]), "+f"(c[1]), "+f"(c[2]), "+f"(c[3])
        : "r"(a.x), "r"(a.y), "r"(a.z), "r"(a.w), "r"(b.x), "r"(b.y));
}
__device__ __forceinline__ float tanh_hw(float x) {
    float y;
    asm("tanh.approx.f32 %0, %1;" : "=f"(y) : "f"(x));
    return y;
}
// r/z gates: single-MUFU sigmoid via tanh.approx (error attenuated by gating)
__device__ __forceinline__ float sig_fast(float x) {
    return fmaf(tanh_hw(0.5f * x), 0.5f, 0.5f);
}
// n gate: accurate tanh (2 MUFU), feeds h directly
__device__ __forceinline__ float tanh_acc(float x) {
    float e = __expf(2.f * x);
    return fmaf(-2.f, __fdividef(1.f, e + 1.f), 1.f);
}
__device__ __forceinline__ float eluf(float x) { return x > 0.f ? x : (__expf(x) - 1.f); }

// ---- setup: pack weights ----
__global__ void s_pack(const float* __restrict__ wh, const float* __restrict__ wi,
                       const float* __restrict__ w1, const float* __restrict__ w2,
                       const float* __restrict__ ew, const float* __restrict__ eb,
                       const float* __restrict__ bi) {
    int id = blockIdx.x * 256 + threadIdx.x;
    if (id < 98304) {
        int lane = id & 31, kt = (id >> 5) & 15, gnt = id >> 9;
        int n = gnt * 8 + (lane >> 2);
        const float* sa;
        const float* sb = 0;
        if (n < 768)        { sa = wh + n * 256; }
        else if (n < 1280)  { sa = wi + (n - 768) * 256; sb = wh + (n - 768) * 256; }
        else                { sa = wi + (n - 1280 + 512) * 256; }
        int k0 = kt * 16 + (lane & 3) * 2;
        float v0 = sa[k0]     + (sb ? sb[k0]     : 0.f);
        float v1 = sa[k0+1]   + (sb ? sb[k0+1]   : 0.f);
        float v2 = sa[k0+8]   + (sb ? sb[k0+8]   : 0.f);
        float v3 = sa[k0+9]   + (sb ? sb[k0+9]   : 0.f);
        uint2 H;
        unsigned dummy;
        H.x = packsplit(v0, v1, dummy);
        H.y = packsplit(v2, v3, dummy);
        int chunk = gnt >> 5, nt = gnt & 31;
        int dest = ((chunk * 16 + (nt >> 1)) * 16 + kt) * 64 + lane * 2 + (nt & 1);
        d_WGhi[dest] = H;
    } else if (id < 106496) {
        int j = id - 98304;
        int lane = j & 31, kt = (j >> 5) & 15, nt = j >> 9;
        const float* src = w1 + (nt * 8 + (lane >> 2)) * 256;
        int k0 = kt * 16 + (lane & 3) * 2;
        uint2 H;
        unsigned dummy;
        H.x = packsplit(src[k0],   src[k0+1], dummy);
        H.y = packsplit(src[k0+8], src[k0+9], dummy);
        d_W1hi[j] = H;
    } else if (id < 110592) {
        int j = id - 106496;
        int lane = j & 31, kt = (j >> 5) & 7, nt = j >> 8;
        const float* src = w2 + (nt * 8 + (lane >> 2)) * 128;
        int k0 = kt * 16 + (lane & 3) * 2;
        uint2 H;
        unsigned dummy;
        H.x = packsplit(src[k0],   src[k0+1], dummy);
        H.y = packsplit(src[k0+8], src[k0+9], dummy);
        d_W2hi[j] = H;
    } else if (id < 111360) {
        int n = id - 110592;
        const float* wr = wi + n * 256;
        float m0 = 0.f, m1 = 0.f, cc = 0.f;
        for (int k = 0; k < 256; k++) {
            float v = wr[k];
            m0 += v * ew[2*k]; m1 += v * ew[2*k+1]; cc += v * eb[k];
        }
        d_Mi[2*n] = m0; d_Mi[2*n+1] = m1; d_ci[n] = cc + bi[n];
    }
}

// =======================================================================
// Persistent fused kernel: CTA = 64 rows (agent, rz-half), 256 threads.
// =======================================================================
extern __shared__ unsigned smem_u[];
__global__ void __launch_bounds__(256, 1) k_all(const float* __restrict__ inp,
                                                const float* __restrict__ bh,
                                                const float* __restrict__ bi,
                                                const float* __restrict__ b1,
                                                const float* __restrict__ b2,
                                                const float* __restrict__ w3,
                                                const float* __restrict__ b3,
                                                const unsigned char* __restrict__ eps,
                                                float* __restrict__ out) {
    uint4* hbuf = (uint4*)smem_u;
    unsigned* fcmem = smem_u + 32768;
    __shared__ int s_ones, s_nz, s_mode;

    int am = blockIdx.x >> 1, rz = blockIdx.x & 1;
    int tid = threadIdx.x;
    int lane = tid & 31, w = tid >> 5;
    int wm = w & 1, wn = w >> 1;
    int lane4 = lane >> 2;
    const uint4* WG4 = (const uint4*)d_WGhi;

    if (tid == 0) { s_ones = 0; s_nz = 0; }
    for (int i = tid; i < 4096; i += 256) hbuf[i] = make_uint4(0, 0, 0, 0);
    __syncthreads();
    for (int i = tid; i < 768; i += 256) {
        unsigned char b = eps[i];
        if ((i & 3) == 3 && b == 0x3f) atomicAdd(&s_ones, 1);
        if ((i & 3) != 0 && b != 0) atomicAdd(&s_nz, 1);
    }
    __syncthreads();
    if (tid == 0) s_mode = (s_ones > 0) ? 2 : (s_nz == 0 ? 1 : 0);
    __syncthreads();
    int mode = s_mode;

    int curb = 0;
    int lmt0 = wm * 2;
    int a0 = (lmt0 * 16) * 32 + lane;
    int a1 = a0 + 512;

    for (int t = 0; t <= 20; t++) {
        // =================== GRU step t ===================
        if (t < 20) {
            bool full = false;
            if (t >= 8) {
                int m = (t - 8) * 64 + am;
                float v = (mode == 2) ? ((const float*)eps)[m]
                        : (mode == 1) ? (float)((const int*)eps)[m]
                        : (float)eps[m];
                full = (v != 0.f);
            }
            const uint4* Ahi = hbuf + curb * 4096;
            const uint4* Alo = Ahi + 2048;
            unsigned* Whi = (unsigned*)(hbuf + (curb ^ 1) * 4096);
            unsigned* Wlo = Whi + 8192;
            const unsigned* RdHi = (const unsigned*)Ahi;
            const unsigned* RdLo = (const unsigned*)Alo;

            int chkR = full ? 3 : 0;
            int chkZ = full ? 4 : 1;

            for (int cg = 0; cg < 4; cg++) {
                int ntp = cg * 4 + wn;
                int bR = ((chkR * 16 + ntp) * 16) * 32 + lane;
                int bZ = ((chkZ * 16 + ntp) * 16) * 32 + lane;
                int bN = ((2    * 16 + ntp) * 16) * 32 + lane;
                int bI = ((5    * 16 + ntp) * 16) * 32 + lane;

                float acc[2][2][4][4];
#pragma unroll
                for (int i = 0; i < 2; i++)
#pragma unroll
                    for (int n = 0; n < 2; n++)
#pragma unroll
                        for (int g = 0; g < 4; g++)
#pragma unroll
                            for (int q = 0; q < 4; q++) acc[i][n][g][q] = 0.f;

                uint4 ahC0 = Ahi[a0], ahC1 = Ahi[a1];
                uint4 alC0 = Alo[a0], alC1 = Alo[a1];
                uint4 WRc = WG4[bR], WZc = WG4[bZ], WNc = WG4[bN];
                uint4 WIc;
                if (full) WIc = WG4[bI];

#pragma unroll 4
                for (int kt = 0; kt < 16; kt++) {
                    int on = ((kt + 1 < 16) ? (kt + 1) : 15) * 32;
                    uint4 WRn = WG4[bR + on], WZn = WG4[bZ + on], WNn = WG4[bN + on];
                    uint4 WIn;
                    if (full) WIn = WG4[bI + on];
                    uint4 ahN0 = Ahi[a0 + on], ahN1 = Ahi[a1 + on];
                    uint4 alN0 = Alo[a0 + on], alN1 = Alo[a1 + on];

                    uint2 Br0 = make_uint2(WRc.x, WRc.y), Br1 = make_uint2(WRc.z, WRc.w);
                    uint2 Bz0 = make_uint2(WZc.x, WZc.y), Bz1 = make_uint2(WZc.z, WZc.w);
                    uint2 Bn0 = make_uint2(WNc.x, WNc.y), Bn1 = make_uint2(WNc.z, WNc.w);

                    mma16816(acc[0][0][0], ahC0, Br0); mma16816(acc[1][0][0], ahC1, Br0);
                    mma16816(acc[0][1][0], ahC0, Br1); mma16816(acc[1][1][0], ahC1, Br1);
                    mma16816(acc[0][0][1], ahC0, Bz0); mma16816(acc[1][0][1], ahC1, Bz0);
                    mma16816(acc[0][1][1], ahC0, Bz1); mma16816(acc[1][1][1], ahC1, Bz1);
                    mma16816(acc[0][0][2], ahC0, Bn0); mma16816(acc[1][0][2], ahC1, Bn0);
                    mma16816(acc[0][1][2], ahC0, Bn1); mma16816(acc[1][1][2], ahC1, Bn1);
                    if (full) {
                        uint2 Bi0 = make_uint2(WIc.x, WIc.y), Bi1 = make_uint2(WIc.z, WIc.w);
                        mma16816(acc[0][0][3], ahC0, Bi0); mma16816(acc[1][0][3], ahC1, Bi0);
                        mma16816(acc[0][1][3], ahC0, Bi1); mma16816(acc[1][1][3], ahC1, Bi1);
                        WIc = WIn;
                    }
                    // state-lo correction, n-gate h-side only (spaced after ah mmas)
                    mma16816(acc[0][0][2], alC0, Bn0); mma16816(acc[1][0][2], alC1, Bn0);
                    mma16816(acc[0][1][2], alC0, Bn1); mma16816(acc[1][1][2], alC1, Bn1);
                    ahC0 = ahN0; ahC1 = ahN1; alC0 = alN0; alC1 = alN1;
                    WRc = WRn; WZc = WZn; WNc = WNn;
                }

                // ---- gate epilogue ----
                int nt0 = cg * 8 + wn * 2;
                float bhr0[2], bhr1[2], bhz0[2], bhz1[2], bhn0[2], bhn1[2];
                float bir0[2], bir1[2], biz0[2], biz1[2], bin0[2], bin1[2];
                float M0a[2][3], M0b[2][3], M1a[2][3], M1b[2][3], C0[2][3], C1[2][3];
                int cc[2];
#pragma unroll
                for (int n = 0; n < 2; n++) {
                    int c = (nt0 + n) * 8 + (lane & 3) * 2;
                    cc[n] = c;
                    bhr0[n] = bh[c];       bhr1[n] = bh[c + 1];
                    bhz0[n] = bh[256 + c]; bhz1[n] = bh[257 + c];
                    bhn0[n] = bh[512 + c]; bhn1[n] = bh[513 + c];
                    if (full) {
                        bir0[n] = bi[c];       bir1[n] = bi[c + 1];
                        biz0[n] = bi[256 + c]; biz1[n] = bi[257 + c];
                        bin0[n] = bi[512 + c]; bin1[n] = bi[513 + c];
                    } else {
#pragma unroll
                        for (int g = 0; g < 3; g++) {
                            int n0 = g * 256 + c;
                            M0a[n][g] = d_Mi[2*n0];     M0b[n][g] = d_Mi[2*n0 + 1];   C0[n][g] = d_ci[n0];
                            M1a[n][g] = d_Mi[2*n0 + 2]; M1b[n][g] = d_Mi[2*n0 + 3];   C1[n][g] = d_ci[n0 + 1];
                        }
                    }
                }

#pragma unroll
                for (int i = 0; i < 2; i++) {
#pragma unroll
                    for (int half = 0; half < 2; half++) {
                        int rloc = (lmt0 + i) * 16 + half * 8 + lane4;
                        int q0 = half * 2;
                        float x0 = 0.f, x1 = 0.f;
                        if (!full) {
                            int b = rz * 64 + rloc;
                            const float* ip = inp + ((b * 64 + am) * 20 + t) * 2;
                            x0 = ip[0]; x1 = ip[1];
                        }
#pragma unroll
                        for (int n = 0; n < 2; n++) {
                            int c = cc[n];
                            int widx = fidx(rloc, c, 16);
                            unsigned uh = RdHi[widx], ul = RdLo[widx];
                            __half2 hh = *(__half2*)&uh, hl = *(__half2*)&ul;
                            float hox = __half2float(__low2half(hh))  + __half2float(__low2half(hl));
                            float hoy = __half2float(__high2half(hh)) + __half2float(__high2half(hl));
                            float r0g, r1g, z0g, z1g, n0g, n1g;
                            if (full) {
                                r0g = sig_fast(acc[i][n][0][q0]   + bir0[n] + bhr0[n]);
                                r1g = sig_fast(acc[i][n][0][q0+1] + bir1[n] + bhr1[n]);
                                z0g = sig_fast(acc[i][n][1][q0]   + biz0[n] + bhz0[n]);
                                z1g = sig_fast(acc[i][n][1][q0+1] + biz1[n] + bhz1[n]);
                                n0g = tanh_acc(acc[i][n][3][q0]   + bin0[n] + r0g * (acc[i][n][2][q0]   + bhn0[n]));
                                n1g = tanh_acc(acc[i][n][3][q0+1] + bin1[n] + r1g * (acc[i][n][2][q0+1] + bhn1[n]));
                            } else {
                                float ir0 = x0 * M0a[n][0] + x1 * M0b[n][0] + C0[n][0];
                                float iz0 = x0 * M0a[n][1] + x1 * M0b[n][1] + C0[n][1];
                                float in0 = x0 * M0a[n][2] + x1 * M0b[n][2] + C0[n][2];
                                float ir1 = x0 * M1a[n][0] + x1 * M1b[n][0] + C1[n][0];
                                float iz1 = x0 * M1a[n][1] + x1 * M1b[n][1] + C1[n][1];
                                float in1 = x0 * M1a[n][2] + x1 * M1b[n][2] + C1[n][2];
                                r0g = sig_fast(ir0 + acc[i][n][0][q0]   + bhr0[n]);
                                r1g = sig_fast(ir1 + acc[i][n][0][q0+1] + bhr1[n]);
                                z0g = sig_fast(iz0 + acc[i][n][1][q0]   + bhz0[n]);
                                z1g = sig_fast(iz1 + acc[i][n][1][q0+1] + bhz1[n]);
                                n0g = tanh_acc(in0 + r0g * (acc[i][n][2][q0]   + bhn0[n]));
                                n1g = tanh_acc(in1 + r1g * (acc[i][n][2][q0+1] + bhn1[n]));
                            }
                            float h0 = (1.f - z0g) * n0g + z0g * hox;
                            float h1 = (1.f - z1g) * n1g + z1g * hoy;
                            unsigned lo, hi = packsplit(h0, h1, lo);
                            Whi[widx] = hi; Wlo[widx] = lo;
                        }
                    }
                }
            }
        }

        // =========== FC head for pred step p = t-1 (overlapped) ===========
        if (t >= 9) {
            int p = t - 1;
            const uint4* Fhi = hbuf + curb * 4096;
            const uint4* Flo = Fhi + 2048;
            unsigned* sY1hi = fcmem;
            unsigned* sY1lo = fcmem + 4096;
            float* sy2 = (float*)fcmem;

            float fa[2][4][4];
#pragma unroll
            for (int i = 0; i < 2; i++)
#pragma unroll
                for (int j = 0; j < 4; j++)
#pragma unroll
                    for (int q = 0; q < 4; q++) fa[i][j][q] = 0.f;
#pragma unroll 2
            for (int kt = 0; kt < 16; kt++) {
                uint4 ah[2], al[2];
#pragma unroll
                for (int i = 0; i < 2; i++) {
                    int base = ((lmt0 + i) * 16 + kt) * 32 + lane;
                    ah[i] = Fhi[base];
                    al[i] = Flo[base];
                }
#pragma unroll
                for (int j = 0; j < 4; j++) {
                    int bb = ((wn * 4 + j) * 16 + kt) * 32 + lane;
                    uint2 Bh = d_W1hi[bb];
#pragma unroll
                    for (int i = 0; i < 2; i++) {
                        mma16816(fa[i][j], ah[i], Bh);
                        mma16816(fa[i][j], al[i], Bh);
                    }
                }
            }
#pragma unroll
            for (int i = 0; i < 2; i++)
#pragma unroll
                for (int j = 0; j < 4; j++) {
                    int rr = wm * 32 + i * 16 + lane4;
                    int cf = wn * 32 + j * 8 + (lane & 3) * 2;
                    float bb0 = b1[cf], bb1 = b1[cf + 1];
                    float v0 = eluf(fa[i][j][0] + bb0);
                    float v1 = eluf(fa[i][j][1] + bb1);
                    unsigned lo, hi = packsplit(v0, v1, lo);
                    int widx = fidx(rr, cf, 8);
                    sY1hi[widx] = hi; sY1lo[widx] = lo;
                    v0 = eluf(fa[i][j][2] + bb0);
                    v1 = eluf(fa[i][j][3] + bb1);
                    hi = packsplit(v0, v1, lo);
                    widx = fidx(rr + 8, cf, 8);
                    sY1hi[widx] = hi; sY1lo[widx] = lo;
                }
            __syncthreads();

            float fb[2][4][4];
#pragma unroll
            for (int i = 0; i < 2; i++)
#pragma unroll
                for (int j = 0; j < 4; j++)
#pragma unroll
                    for (int q = 0; q < 4; q++) fb[i][j][q] = 0.f;
            const uint4* sY1hi4 = (const uint4*)sY1hi;
            const uint4* sY1lo4 = (const uint4*)sY1lo;
#pragma unroll 2
            for (int kt = 0; kt < 8; kt++) {
                uint4 ah[2], al[2];
#pragma unroll
                for (int i = 0; i < 2; i++) {
                    int base = ((wm * 2 + i) * 8 + kt) * 32 + lane;
                    ah[i] = sY1hi4[base];
                    al[i] = sY1lo4[base];
                }
#pragma unroll
                for (int j = 0; j < 4; j++) {
                    int bb = ((wn * 4 + j) * 8 + kt) * 32 + lane;
                    uint2 Bh = d_W2hi[bb];
#pragma unroll
                    for (int i = 0; i < 2; i++) {
                        mma16816(fb[i][j], ah[i], Bh);
                        mma16816(fb[i][j], al[i], Bh);
                    }
                }
            }
            __syncthreads();

#pragma unroll
            for (int i = 0; i < 2; i++)
#pragma unroll
                for (int j = 0; j < 4; j++) {
                    int rr = wm * 32 + i * 16 + lane4;
                    int cf = wn * 32 + j * 8 + (lane & 3) * 2;
                    float bb0 = b2[cf], bb1 = b2[cf + 1];
                    sy2[rr * 132 + cf]           = eluf(fb[i][j][0] + bb0);
                    sy2[rr * 132 + cf + 1]       = eluf(fb[i][j][1] + bb1);
                    sy2[(rr + 8) * 132 + cf]     = eluf(fb[i][j][2] + bb0);
                    sy2[(rr + 8) * 132 + cf + 1] = eluf(fb[i][j][3] + bb1);
                }
            __syncthreads();

            if (tid < 128) {
                int rl = tid >> 1, cr = tid & 1;
                const float* wr = w3 + cr * 128;
                float s = b3[cr];
#pragma unroll 8
                for (int k = 0; k < 128; k++) s += sy2[rl * 132 + k] * __ldg(wr + k);
                int b = rz * 64 + rl;
                float gv = inp[((b * 64 + am) * 20 + p) * 2 + cr];
                out[((b * 64 + am) * 12 + (p - 8)) * 2 + cr] = (gv != 0.f) ? s : 0.f;
            }
        }

        __syncthreads();
        if (t < 20) curb ^= 1;
    }
}

extern "C" void kernel_launch(void* const* d_in, const int* in_sizes, int n_in,
                              void* d_out, int out_size) {
    int sh = (n_in >= 15 && in_sizes[1] <= 4) ? 0 : -1;
    const float* inputs = (const float*)d_in[0];
    const unsigned char* eps = (const unsigned char*)d_in[2 + sh];
    const float* ew = (const float*)d_in[3 + sh];
    const float* eb = (const float*)d_in[4 + sh];
    const float* wi = (const float*)d_in[5 + sh];
    const float* wh = (const float*)d_in[6 + sh];
    const float* bi = (const float*)d_in[7 + sh];
    const float* bh = (const float*)d_in[8 + sh];
    const float* w1 = (const float*)d_in[9 + sh];
    const float* b1 = (const float*)d_in[10 + sh];
    const float* w2 = (const float*)d_in[11 + sh];
    const float* b2 = (const float*)d_in[12 + sh];
    const float* w3 = (const float*)d_in[13 + sh];
    const float* b3 = (const float*)d_in[14 + sh];
    float* out = (float*)d_out;

    static int smem_set = 0;
    if (!smem_set) {
        cudaFuncSetAttribute(k_all, cudaFuncAttributeMaxDynamicSharedMemorySize, 165120);
        smem_set = 1;
    }

    s_pack<<<435, 256>>>(wh, wi, w1, w2, ew, eb, bi);
    k_all<<<128, 256, 165120>>>(inputs, bh, bi, b1, b2, w3, b3, eps, out);
}

// round 17
// speedup vs baseline: 1.2418x; 1.0757x over previous
#include <cuda_runtime.h>
#include <cuda_fp16.h>

// ---- static device scratch ----
__device__ uint2 d_WGhi[192*16*32];   // GRU B frags, paired-nt interleaved
__device__ uint2 d_W1hi[16*16*32];
__device__ uint2 d_W2hi[16*8*32];
__device__ float d_Mi[768*2];
__device__ float d_ci[768];

// ---- helpers ----
__device__ __forceinline__ unsigned packsplit(float v0, float v1, unsigned &lo) {
    __half h0 = __float2half(v0);
    __half h1 = __float2half(v1);
    __half l0 = __float2half(v0 - __half2float(h0));
    __half l1 = __float2half(v1 - __half2float(h1));
    lo = ((unsigned)__half_as_ushort(l1) << 16) | (unsigned)__half_as_ushort(l0);
    return ((unsigned)__half_as_ushort(h1) << 16) | (unsigned)__half_as_ushort(h0);
}
__device__ __forceinline__ int fidx(int r, int c, int KT) {
    return (((r >> 4) * KT + (c >> 4)) * 32 + (r & 7) * 4 + ((c & 7) >> 1)) * 4
           + ((r >> 3) & 1) + (((c >> 3) & 1) << 1);
}
__device__ __forceinline__ void mma16816(float (&c)[4], const uint4 a, const uint2 b) {
    asm volatile(
        "mma.sync.aligned.m16n8k16.row.col.f32.f16.f16.f32 "
        "{%0,%1,%2,%3},{%4,%5,%6,%7},{%8,%9},{%0,%1,%2,%3};\n"
        : "+f"(c[0]), "+f"(c[1]), "+f"(c[2]), "+f"(c[3])
        : "r"(a.x), "r"(a.y), "r"(a.z), "r"(a.w), "r"(b.x), "r"(b.y));
}
__device__ __forceinline__ float tanh_hw(float x) {
    float y;
    asm("tanh.approx.f32 %0, %1;" : "=f"(y) : "f"(x));
    return y;
}
// r/z gates: single-MUFU sigmoid via tanh.approx
__device__ __forceinline__ float sig_fast(float x) {
    return fmaf(tanh_hw(0.5f * x), 0.5f, 0.5f);
}
__device__ __forceinline__ float eluf(float x) { return x > 0.f ? x : (__expf(x) - 1.f); }

// ---- setup: pack weights ----
__global__ void s_pack(const float* __restrict__ wh, const float* __restrict__ wi,
                       const float* __restrict__ w1, const float* __restrict__ w2,
                       const float* __restrict__ ew, const float* __restrict__ eb,
                       const float* __restrict__ bi) {
    int id = blockIdx.x * 256 + threadIdx.x;
    if (id < 98304) {
        int lane = id & 31, kt = (id >> 5) & 15, gnt = id >> 9;
        int n = gnt * 8 + (lane >> 2);
        const float* sa;
        const float* sb = 0;
        if (n < 768)        { sa = wh + n * 256; }
        else if (n < 1280)  { sa = wi + (n - 768) * 256; sb = wh + (n - 768) * 256; }
        else                { sa = wi + (n - 1280 + 512) * 256; }
        int k0 = kt * 16 + (lane & 3) * 2;
        float v0 = sa[k0]     + (sb ? sb[k0]     : 0.f);
        float v1 = sa[k0+1]   + (sb ? sb[k0+1]   : 0.f);
        float v2 = sa[k0+8]   + (sb ? sb[k0+8]   : 0.f);
        float v3 = sa[k0+9]   + (sb ? sb[k0+9]   : 0.f);
        uint2 H;
        unsigned dummy;
        H.x = packsplit(v0, v1, dummy);
        H.y = packsplit(v2, v3, dummy);
        int chunk = gnt >> 5, nt = gnt & 31;
        int dest = ((chunk * 16 + (nt >> 1)) * 16 + kt) * 64 + lane * 2 + (nt & 1);
        d_WGhi[dest] = H;
    } else if (id < 106496) {
        int j = id - 98304;
        int lane = j & 31, kt = (j >> 5) & 15, nt = j >> 9;
        const float* src = w1 + (nt * 8 + (lane >> 2)) * 256;
        int k0 = kt * 16 + (lane & 3) * 2;
        uint2 H;
        unsigned dummy;
        H.x = packsplit(src[k0],   src[k0+1], dummy);
        H.y = packsplit(src[k0+8], src[k0+9], dummy);
        d_W1hi[j] = H;
    } else if (id < 110592) {
        int j = id - 106496;
        int lane = j & 31, kt = (j >> 5) & 7, nt = j >> 8;
        const float* src = w2 + (nt * 8 + (lane >> 2)) * 128;
        int k0 = kt * 16 + (lane & 3) * 2;
        uint2 H;
        unsigned dummy;
        H.x = packsplit(src[k0],   src[k0+1], dummy);
        H.y = packsplit(src[k0+8], src[k0+9], dummy);
        d_W2hi[j] = H;
    } else if (id < 111360) {
        int n = id - 110592;
        const float* wr = wi + n * 256;
        float m0 = 0.f, m1 = 0.f, cc = 0.f;
        for (int k = 0; k < 256; k++) {
            float v = wr[k];
            m0 += v * ew[2*k]; m1 += v * ew[2*k+1]; cc += v * eb[k];
        }
        d_Mi[2*n] = m0; d_Mi[2*n+1] = m1; d_ci[n] = cc + bi[n];
    }
}

// =======================================================================
// Persistent fused kernel: CTA = 64 rows (agent, rz-half), 256 threads.
// =======================================================================
extern __shared__ unsigned smem_u[];
__global__ void __launch_bounds__(256, 1) k_all(const float* __restrict__ inp,
                                                const float* __restrict__ bh,
                                                const float* __restrict__ bi,
                                                const float* __restrict__ b1,
                                                const float* __restrict__ b2,
                                                const float* __restrict__ w3,
                                                const float* __restrict__ b3,
                                                const unsigned char* __restrict__ eps,
                                                float* __restrict__ out) {
    uint4* hbuf = (uint4*)smem_u;
    unsigned* fcmem = smem_u + 32768;
    __shared__ int s_ones, s_nz, s_mode;

    int am = blockIdx.x >> 1, rz = blockIdx.x & 1;
    int tid = threadIdx.x;
    int lane = tid & 31, w = tid >> 5;
    int wm = w & 1, wn = w >> 1;
    int lane4 = lane >> 2;
    const uint4* WG4 = (const uint4*)d_WGhi;

    if (tid == 0) { s_ones = 0; s_nz = 0; }
    for (int i = tid; i < 4096; i += 256) hbuf[i] = make_uint4(0, 0, 0, 0);
    __syncthreads();
    for (int i = tid; i < 768; i += 256) {
        unsigned char b = eps[i];
        if ((i & 3) == 3 && b == 0x3f) atomicAdd(&s_ones, 1);
        if ((i & 3) != 0 && b != 0) atomicAdd(&s_nz, 1);
    }
    __syncthreads();
    if (tid == 0) s_mode = (s_ones > 0) ? 2 : (s_nz == 0 ? 1 : 0);
    __syncthreads();
    int mode = s_mode;

    int curb = 0;
    int lmt0 = wm * 2;
    int a0 = (lmt0 * 16) * 32 + lane;
    int a1 = a0 + 512;

    for (int t = 0; t <= 20; t++) {
        // =================== GRU step t ===================
        if (t < 20) {
            bool full = false;
            if (t >= 8) {
                int m = (t - 8) * 64 + am;
                float v = (mode == 2) ? ((const float*)eps)[m]
                        : (mode == 1) ? (float)((const int*)eps)[m]
                        : (float)eps[m];
                full = (v != 0.f);
            }
            const uint4* Ahi = hbuf + curb * 4096;
            const uint4* Alo = Ahi + 2048;
            unsigned* Whi = (unsigned*)(hbuf + (curb ^ 1) * 4096);
            unsigned* Wlo = Whi + 8192;
            const unsigned* RdHi = (const unsigned*)Ahi;
            const unsigned* RdLo = (const unsigned*)Alo;

            int chkR = full ? 3 : 0;
            int chkZ = full ? 4 : 1;

            for (int cg = 0; cg < 4; cg++) {
                int ntp = cg * 4 + wn;
                int bR = ((chkR * 16 + ntp) * 16) * 32 + lane;
                int bZ = ((chkZ * 16 + ntp) * 16) * 32 + lane;
                int bN = ((2    * 16 + ntp) * 16) * 32 + lane;
                int bI = ((5    * 16 + ntp) * 16) * 32 + lane;

                float acc[2][2][4][4];
#pragma unroll
                for (int i = 0; i < 2; i++)
#pragma unroll
                    for (int n = 0; n < 2; n++)
#pragma unroll
                        for (int g = 0; g < 4; g++)
#pragma unroll
                            for (int q = 0; q < 4; q++) acc[i][n][g][q] = 0.f;

                uint4 ahC0 = Ahi[a0], ahC1 = Ahi[a1];
                uint4 alC0 = Alo[a0], alC1 = Alo[a1];
                uint4 WRc = WG4[bR], WZc = WG4[bZ], WNc = WG4[bN];
                uint4 WIc;
                if (full) WIc = WG4[bI];

#pragma unroll 4
                for (int kt = 0; kt < 16; kt++) {
                    int on = ((kt + 1 < 16) ? (kt + 1) : 15) * 32;
                    uint4 WRn = WG4[bR + on], WZn = WG4[bZ + on], WNn = WG4[bN + on];
                    uint4 WIn;
                    if (full) WIn = WG4[bI + on];
                    uint4 ahN0 = Ahi[a0 + on], ahN1 = Ahi[a1 + on];
                    uint4 alN0 = Alo[a0 + on], alN1 = Alo[a1 + on];

                    uint2 Br0 = make_uint2(WRc.x, WRc.y), Br1 = make_uint2(WRc.z, WRc.w);
                    uint2 Bz0 = make_uint2(WZc.x, WZc.y), Bz1 = make_uint2(WZc.z, WZc.w);
                    uint2 Bn0 = make_uint2(WNc.x, WNc.y), Bn1 = make_uint2(WNc.z, WNc.w);

                    mma16816(acc[0][0][0], ahC0, Br0); mma16816(acc[1][0][0], ahC1, Br0);
                    mma16816(acc[0][1][0], ahC0, Br1); mma16816(acc[1][1][0], ahC1, Br1);
                    mma16816(acc[0][0][1], ahC0, Bz0); mma16816(acc[1][0][1], ahC1, Bz0);
                    mma16816(acc[0][1][1], ahC0, Bz1); mma16816(acc[1][1][1], ahC1, Bz1);
                    mma16816(acc[0][0][2], ahC0, Bn0); mma16816(acc[1][0][2], ahC1, Bn0);
                    mma16816(acc[0][1][2], ahC0, Bn1); mma16816(acc[1][1][2], ahC1, Bn1);
                    if (full) {
                        uint2 Bi0 = make_uint2(WIc.x, WIc.y), Bi1 = make_uint2(WIc.z, WIc.w);
                        mma16816(acc[0][0][3], ahC0, Bi0); mma16816(acc[1][0][3], ahC1, Bi0);
                        mma16816(acc[0][1][3], ahC0, Bi1); mma16816(acc[1][1][3], ahC1, Bi1);
                        WIc = WIn;
                    }
                    // state-lo correction, n-gate h-side only
                    mma16816(acc[0][0][2], alC0, Bn0); mma16816(acc[1][0][2], alC1, Bn0);
                    mma16816(acc[0][1][2], alC0, Bn1); mma16816(acc[1][1][2], alC1, Bn1);
                    ahC0 = ahN0; ahC1 = ahN1; alC0 = alN0; alC1 = alN1;
                    WRc = WRn; WZc = WZn; WNc = WNn;
                }

                // ---- gate epilogue ----
                int nt0 = cg * 8 + wn * 2;
                float bhr0[2], bhr1[2], bhz0[2], bhz1[2], bhn0[2], bhn1[2];
                float bir0[2], bir1[2], biz0[2], biz1[2], bin0[2], bin1[2];
                float M0a[2][3], M0b[2][3], M1a[2][3], M1b[2][3], C0[2][3], C1[2][3];
                int cc[2];
#pragma unroll
                for (int n = 0; n < 2; n++) {
                    int c = (nt0 + n) * 8 + (lane & 3) * 2;
                    cc[n] = c;
                    bhr0[n] = bh[c];       bhr1[n] = bh[c + 1];
                    bhz0[n] = bh[256 + c]; bhz1[n] = bh[257 + c];
                    bhn0[n] = bh[512 + c]; bhn1[n] = bh[513 + c];
                    if (full) {
                        bir0[n] = bi[c];       bir1[n] = bi[c + 1];
                        biz0[n] = bi[256 + c]; biz1[n] = bi[257 + c];
                        bin0[n] = bi[512 + c]; bin1[n] = bi[513 + c];
                    } else {
#pragma unroll
                        for (int g = 0; g < 3; g++) {
                            int n0 = g * 256 + c;
                            M0a[n][g] = d_Mi[2*n0];     M0b[n][g] = d_Mi[2*n0 + 1];   C0[n][g] = d_ci[n0];
                            M1a[n][g] = d_Mi[2*n0 + 2]; M1b[n][g] = d_Mi[2*n0 + 3];   C1[n][g] = d_ci[n0 + 1];
                        }
                    }
                }

#pragma unroll
                for (int i = 0; i < 2; i++) {
#pragma unroll
                    for (int half = 0; half < 2; half++) {
                        int rloc = (lmt0 + i) * 16 + half * 8 + lane4;
                        int q0 = half * 2;
                        float x0 = 0.f, x1 = 0.f;
                        if (!full) {
                            int b = rz * 64 + rloc;
                            const float* ip = inp + ((b * 64 + am) * 20 + t) * 2;
                            x0 = ip[0]; x1 = ip[1];
                        }
#pragma unroll
                        for (int n = 0; n < 2; n++) {
                            int c = cc[n];
                            int widx = fidx(rloc, c, 16);
                            unsigned uh = RdHi[widx], ul = RdLo[widx];
                            __half2 hh = *(__half2*)&uh, hl = *(__half2*)&ul;
                            float hox = __half2float(__low2half(hh))  + __half2float(__low2half(hl));
                            float hoy = __half2float(__high2half(hh)) + __half2float(__high2half(hl));
                            float r0g, r1g, z0g, z1g, n0g, n1g;
                            if (full) {
                                r0g = sig_fast(acc[i][n][0][q0]   + bir0[n] + bhr0[n]);
                                r1g = sig_fast(acc[i][n][0][q0+1] + bir1[n] + bhr1[n]);
                                z0g = sig_fast(acc[i][n][1][q0]   + biz0[n] + bhz0[n]);
                                z1g = sig_fast(acc[i][n][1][q0+1] + biz1[n] + bhz1[n]);
                                n0g = tanh_hw(acc[i][n][3][q0]   + bin0[n] + r0g * (acc[i][n][2][q0]   + bhn0[n]));
                                n1g = tanh_hw(acc[i][n][3][q0+1] + bin1[n] + r1g * (acc[i][n][2][q0+1] + bhn1[n]));
                            } else {
                                float ir0 = x0 * M0a[n][0] + x1 * M0b[n][0] + C0[n][0];
                                float iz0 = x0 * M0a[n][1] + x1 * M0b[n][1] + C0[n][1];
                                float in0 = x0 * M0a[n][2] + x1 * M0b[n][2] + C0[n][2];
                                float ir1 = x0 * M1a[n][0] + x1 * M1b[n][0] + C1[n][0];
                                float iz1 = x0 * M1a[n][1] + x1 * M1b[n][1] + C1[n][1];
                                float in1 = x0 * M1a[n][2] + x1 * M1b[n][2] + C1[n][2];
                                r0g = sig_fast(ir0 + acc[i][n][0][q0]   + bhr0[n]);
                                r1g = sig_fast(ir1 + acc[i][n][0][q0+1] + bhr1[n]);
                                z0g = sig_fast(iz0 + acc[i][n][1][q0]   + bhz0[n]);
                                z1g = sig_fast(iz1 + acc[i][n][1][q0+1] + bhz1[n]);
                                n0g = tanh_hw(in0 + r0g * (acc[i][n][2][q0]   + bhn0[n]));
                                n1g = tanh_hw(in1 + r1g * (acc[i][n][2][q0+1] + bhn1[n]));
                            }
                            float h0 = (1.f - z0g) * n0g + z0g * hox;
                            float h1 = (1.f - z1g) * n1g + z1g * hoy;
                            unsigned lo, hi = packsplit(h0, h1, lo);
                            Whi[widx] = hi; Wlo[widx] = lo;
                        }
                    }
                }
            }
        }

        // =========== FC head for pred step p = t-1 (overlapped) ===========
        if (t >= 9) {
            int p = t - 1;
            const uint4* Fhi = hbuf + curb * 4096;
            const uint4* Flo = Fhi + 2048;
            unsigned* sY1hi = fcmem;
            unsigned* sY1lo = fcmem + 4096;
            float* sy2 = (float*)fcmem;

            float fa[2][4][4];
#pragma unroll
            for (int i = 0; i < 2; i++)
#pragma unroll
                for (int j = 0; j < 4; j++)
#pragma unroll
                    for (int q = 0; q < 4; q++) fa[i][j][q] = 0.f;
#pragma unroll 2
            for (int kt = 0; kt < 16; kt++) {
                uint4 ah[2], al[2];
#pragma unroll
                for (int i = 0; i < 2; i++) {
                    int base = ((lmt0 + i) * 16 + kt) * 32 + lane;
                    ah[i] = Fhi[base];
                    al[i] = Flo[base];
                }
#pragma unroll
                for (int j = 0; j < 4; j++) {
                    int bb = ((wn * 4 + j) * 16 + kt) * 32 + lane;
                    uint2 Bh = d_W1hi[bb];
#pragma unroll
                    for (int i = 0; i < 2; i++) {
                        mma16816(fa[i][j], ah[i], Bh);
                        mma16816(fa[i][j], al[i], Bh);
                    }
                }
            }
#pragma unroll
            for (int i = 0; i < 2; i++)
#pragma unroll
                for (int j = 0; j < 4; j++) {
                    int rr = wm * 32 + i * 16 + lane4;
                    int cf = wn * 32 + j * 8 + (lane & 3) * 2;
                    float bb0 = b1[cf], bb1 = b1[cf + 1];
                    float v0 = eluf(fa[i][j][0] + bb0);
                    float v1 = eluf(fa[i][j][1] + bb1);
                    unsigned lo, hi = packsplit(v0, v1, lo);
                    int widx = fidx(rr, cf, 8);
                    sY1hi[widx] = hi; sY1lo[widx] = lo;
                    v0 = eluf(fa[i][j][2] + bb0);
                    v1 = eluf(fa[i][j][3] + bb1);
                    hi = packsplit(v0, v1, lo);
                    widx = fidx(rr + 8, cf, 8);
                    sY1hi[widx] = hi; sY1lo[widx] = lo;
                }
            __syncthreads();

            float fb[2][4][4];
#pragma unroll
            for (int i = 0; i < 2; i++)
#pragma unroll
                for (int j = 0; j < 4; j++)
#pragma unroll
                    for (int q = 0; q < 4; q++) fb[i][j][q] = 0.f;
            const uint4* sY1hi4 = (const uint4*)sY1hi;
            const uint4* sY1lo4 = (const uint4*)sY1lo;
#pragma unroll 2
            for (int kt = 0; kt < 8; kt++) {
                uint4 ah[2], al[2];
#pragma unroll
                for (int i = 0; i < 2; i++) {
                    int base = ((wm * 2 + i) * 8 + kt) * 32 + lane;
                    ah[i] = sY1hi4[base];
                    al[i] = sY1lo4[base];
                }
#pragma unroll
                for (int j = 0; j < 4; j++) {
                    int bb = ((wn * 4 + j) * 8 + kt) * 32 + lane;
                    uint2 Bh = d_W2hi[bb];
#pragma unroll
                    for (int i = 0; i < 2; i++) {
                        mma16816(fb[i][j], ah[i], Bh);
                        mma16816(fb[i][j], al[i], Bh);
                    }
                }
            }
            __syncthreads();

#pragma unroll
            for (int i = 0; i < 2; i++)
#pragma unroll
                for (int j = 0; j < 4; j++) {
                    int rr = wm * 32 + i * 16 + lane4;
                    int cf = wn * 32 + j * 8 + (lane & 3) * 2;
                    float bb0 = b2[cf], bb1 = b2[cf + 1];
                    sy2[rr * 132 + cf]           = eluf(fb[i][j][0] + bb0);
                    sy2[rr * 132 + cf + 1]       = eluf(fb[i][j][1] + bb1);
                    sy2[(rr + 8) * 132 + cf]     = eluf(fb[i][j][2] + bb0);
                    sy2[(rr + 8) * 132 + cf + 1] = eluf(fb[i][j][3] + bb1);
                }
            __syncthreads();

            // ---- fc3 + gt mask: split-k across thread pairs ----
            {
                int rl = tid >> 2;
                int sub = tid & 3;
                int cr = sub & 1, kh = sub >> 1;
                const float* wr = w3 + cr * 128 + kh * 64;
                const float* yr = sy2 + rl * 132 + kh * 64;
                float s = 0.f;
#pragma unroll 8
                for (int k = 0; k < 64; k++) s += yr[k] * __ldg(wr + k);
                s += __shfl_xor_sync(0xFFFFFFFFu, s, 2);
                if (kh == 0) {
                    int b = rz * 64 + rl;
                    float gv = inp[((b * 64 + am) * 20 + p) * 2 + cr];
                    out[((b * 64 + am) * 12 + (p - 8)) * 2 + cr] =
                        (gv != 0.f) ? (s + b3[cr]) : 0.f;
                }
            }
        }

        __syncthreads();
        if (t < 20) curb ^= 1;
    }
}

extern "C" void kernel_launch(void* const* d_in, const int* in_sizes, int n_in,
                              void* d_out, int out_size) {
    int sh = (n_in >= 15 && in_sizes[1] <= 4) ? 0 : -1;
    const float* inputs = (const float*)d_in[0];
    const unsigned char* eps = (const unsigned char*)d_in[2 + sh];
    const float* ew = (const float*)d_in[3 + sh];
    const float* eb = (const float*)d_in[4 + sh];
    const float* wi = (const float*)d_in[5 + sh];
    const float* wh = (const float*)d_in[6 + sh];
    const float* bi = (const float*)d_in[7 + sh];
    const float* bh = (const float*)d_in[8 + sh];
    const float* w1 = (const float*)d_in[9 + sh];
    const float* b1 = (const float*)d_in[10 + sh];
    const float* w2 = (const float*)d_in[11 + sh];
    const float* b2 = (const float*)d_in[12 + sh];
    const float* w3 = (const float*)d_in[13 + sh];
    const float* b3 = (const float*)d_in[14 + sh];
    float* out = (float*)d_out;

    static int smem_set = 0;
    if (!smem_set) {
        cudaFuncSetAttribute(k_all, cudaFuncAttributeMaxDynamicSharedMemorySize, 165120);
        smem_set = 1;
    }

    s_pack<<<435, 256>>>(wh, wi, w1, w2, ew, eb, bi);
    k_all<<<128, 256, 165120>>>(inputs, bh, bi, b1, b2, w3, b3, eps, out);
}